// round 11
// baseline (speedup 1.0000x reference)
#include <cuda_runtime.h>
#include <cstdint>

#define BATCH   2
#define SEQ     2048
#define DMODEL  1024
#define NH      16
#define HD      64
#define NTOK    (BATCH*SEQ)

typedef unsigned long long ull;
typedef unsigned int u32;

#define SOFTMAX_C 0.045084220027f   // (1/32) * log2(e)

// ---------------- scratch (static device globals: allocation-free) ----------------
__device__ float g_q  [BATCH*NH*SEQ*HD];   // [bh][s][d]  (pre-scaled by SOFTMAX_C)
__device__ float g_k  [BATCH*NH*SEQ*HD];   // [bh][s][d]
__device__ float g_v  [BATCH*NH*HD*SEQ];   // [bh][d][s]
__device__ float g_aoh[NTOK*DMODEL];
__device__ float g_aol[NTOK*DMODEL];
__device__ float g_woh[DMODEL*DMODEL];
__device__ float g_wol[DMODEL*DMODEL];
__device__ u32   g_mbits[BATCH*SEQ*(SEQ/32)];

// ---------------- helpers ----------------
__device__ __forceinline__ float ex2f(float x){
    float y; asm("ex2.approx.ftz.f32 %0,%1;" : "=f"(y) : "f"(x)); return y;
}
__device__ __forceinline__ u32 cvt_tf32(float x){
    u32 y; asm("cvt.rna.tf32.f32 %0,%1;" : "=r"(y) : "f"(x)); return y;
}
__device__ __forceinline__ float round_tf32(float x){
    return __uint_as_float(cvt_tf32(x));
}
__device__ __forceinline__ void cpa16(u32 dst, const void* src){
    asm volatile("cp.async.cg.shared.global [%0], [%1], 16;" :: "r"(dst), "l"(src));
}
#define CPA_COMMIT() asm volatile("cp.async.commit_group;" ::: "memory")
#define CPA_WAIT0()  asm volatile("cp.async.wait_group 0;" ::: "memory")
#define CPA_WAIT1()  asm volatile("cp.async.wait_group 1;" ::: "memory")

__device__ __forceinline__ u32 smem_u32(const void* p){
    u32 a; asm("{ .reg .u64 t; cvta.to.shared.u64 t, %1; cvt.u32.u64 %0, t; }" : "=r"(a) : "l"(p));
    return a;
}
// mma.sync m16n8k8 tf32
__device__ __forceinline__ void mma_tf32(float* d, const u32* a, u32 b0, u32 b1){
    asm volatile("mma.sync.aligned.m16n8k8.row.col.f32.tf32.tf32.f32 "
        "{%0,%1,%2,%3},{%4,%5,%6,%7},{%8,%9},{%0,%1,%2,%3};"
        : "+f"(d[0]), "+f"(d[1]), "+f"(d[2]), "+f"(d[3])
        : "r"(a[0]), "r"(a[1]), "r"(a[2]), "r"(a[3]), "r"(b0), "r"(b1));
}
__device__ __forceinline__ void ldsm4(u32& r0, u32& r1, u32& r2, u32& r3, u32 addr){
    asm volatile("ldmatrix.sync.aligned.m8n8.x4.shared.b16 {%0,%1,%2,%3}, [%4];"
        : "=r"(r0), "=r"(r1), "=r"(r2), "=r"(r3) : "r"(addr));
}
__device__ __forceinline__ void ldsm2(u32& r0, u32& r1, u32 addr){
    asm volatile("ldmatrix.sync.aligned.m8n8.x2.shared.b16 {%0,%1}, [%2];"
        : "=r"(r0), "=r"(r1) : "r"(addr));
}

// =====================================================================
// Kernel 0: split Wo into tf32 hi/lo
// =====================================================================
__global__ void wsplit_kernel(const float* __restrict__ W)
{
    const int i = blockIdx.x * 256 + threadIdx.x;
    const float4 w = ((const float4*)W)[i];
    float4 h, l;
    h.x = round_tf32(w.x); l.x = round_tf32(w.x - h.x);
    h.y = round_tf32(w.y); l.y = round_tf32(w.y - h.y);
    h.z = round_tf32(w.z); l.z = round_tf32(w.z - h.z);
    h.w = round_tf32(w.w); l.w = round_tf32(w.w - h.w);
    ((float4*)g_woh)[i] = h;
    ((float4*)g_wol)[i] = l;
}

// =====================================================================
// Kernel 1: QKV projection via tf32 mma. grid (NTOK/128, 1, 3).
// Q output pre-scaled by SOFTMAX_C. V written d-major.
// =====================================================================
#define PJ_WST 0
#define PJ_BS  17408
#define PJ_X0  17664
#define PJ_X1  52480
#define PJ_SMEM 87296

__device__ __forceinline__ void pj_load_x(u32 xb, const float* __restrict__ x,
                                          int q0, int hofs, int tid)
{
    #pragma unroll
    for (int l2 = 0; l2 < 8; ++l2) {
        const int i = tid + l2*256;
        const int row = i >> 4, c4 = i & 15;
        cpa16(xb + (u32)(row*68 + c4*4)*4,
              x + (size_t)(q0 + row)*DMODEL + hofs + c4*4);
    }
}

__global__ __launch_bounds__(256)
void proj_mma(const float* __restrict__ xq, const float* __restrict__ xk,
              const float* __restrict__ xv,
              const float* __restrict__ Wq_, const float* __restrict__ bq_,
              const float* __restrict__ Wk_, const float* __restrict__ bk_,
              const float* __restrict__ Wv_, const float* __restrict__ bv_,
              float* __restrict__ outq, float* __restrict__ outk,
              float* __restrict__ outv)
{
    extern __shared__ float smf[];
    const u32 smem_base = smem_u32(smf);
    const int tid = threadIdx.x;
    const int wid = tid >> 5, lane = tid & 31;
    const int r = lane >> 2, t = lane & 3;
    const int z = blockIdx.z;
    const float* x  = (z == 0) ? xq  : (z == 1) ? xk  : xv;
    const float* W  = (z == 0) ? Wq_ : (z == 1) ? Wk_ : Wv_;
    const float* bi = (z == 0) ? bq_ : (z == 1) ? bk_ : bv_;
    float* outg     = (z == 0) ? outq : (z == 1) ? outk : outv;
    const float qscale = (z == 0) ? SOFTMAX_C : 1.0f;
    const int q0 = blockIdx.x * 128;
    const int bb = q0 >> 11;
    const int s0 = q0 & (SEQ - 1);
    const int rw = wid*16 + r;

    for (int idx = tid; idx < 4096; idx += 256)
        smf[PJ_WST/4 + (idx >> 6)*68 + (idx & 63)] = W[idx];
    if (tid < 64) smf[PJ_BS/4 + tid] = bi[tid];

    pj_load_x(smem_base + PJ_X0, x, q0, 0, tid);
    CPA_COMMIT();
    __syncthreads();

    for (int h = 0; h < 16; ++h) {
        const int st = h & 1;
        CPA_WAIT0();
        __syncthreads();
        if (h < 15) {
            pj_load_x(smem_base + (st ? PJ_X0 : PJ_X1), x, q0, (h+1)*64, tid);
            CPA_COMMIT();
        }

        const float* Xs = smf + (st ? PJ_X1 : PJ_X0)/4;
        u32 af[8][4];
        #pragma unroll
        for (int kk = 0; kk < 8; ++kk) {
            af[kk][0] = __float_as_uint(Xs[(rw    )*68 + kk*8 + t    ]);
            af[kk][1] = __float_as_uint(Xs[(rw + 8)*68 + kk*8 + t    ]);
            af[kk][2] = __float_as_uint(Xs[(rw    )*68 + kk*8 + t + 4]);
            af[kk][3] = __float_as_uint(Xs[(rw + 8)*68 + kk*8 + t + 4]);
        }

        float acc[8][4];
        #pragma unroll
        for (int i = 0; i < 8; ++i)
            #pragma unroll
            for (int j = 0; j < 4; ++j) acc[i][j] = 0.f;

        const float* Wt = smf + PJ_WST/4;
        #pragma unroll
        for (int kk = 0; kk < 8; ++kk) {
            #pragma unroll
            for (int nt = 0; nt < 8; ++nt) {
                const u32 b0 = __float_as_uint(Wt[(nt*8 + r)*68 + kk*8 + t    ]);
                const u32 b1 = __float_as_uint(Wt[(nt*8 + r)*68 + kk*8 + t + 4]);
                mma_tf32(acc[nt], af[kk], b0, b1);
            }
        }

        const float* bsp = smf + PJ_BS/4;
        if (z < 2) {
            float* orow1 = outg + ((size_t)(bb*NH + h)*SEQ + s0 + rw    )*64;
            float* orow2 = outg + ((size_t)(bb*NH + h)*SEQ + s0 + rw + 8)*64;
            #pragma unroll
            for (int nt = 0; nt < 8; ++nt) {
                const int n = nt*8 + 2*t;
                const float b0 = bsp[n], b1 = bsp[n+1];
                *(float2*)(orow1 + n) = make_float2(round_tf32((acc[nt][0]+b0)*qscale),
                                                    round_tf32((acc[nt][1]+b1)*qscale));
                *(float2*)(orow2 + n) = make_float2(round_tf32((acc[nt][2]+b0)*qscale),
                                                    round_tf32((acc[nt][3]+b1)*qscale));
            }
        } else {
            __syncthreads();
            float* Ts = smf + (st ? PJ_X1 : PJ_X0)/4;
            #pragma unroll
            for (int nt = 0; nt < 8; ++nt) {
                const int n = nt*8 + 2*t;
                const float b0 = bsp[n], b1 = bsp[n+1];
                Ts[(n  )*132 + rw    ] = round_tf32(acc[nt][0]+b0);
                Ts[(n+1)*132 + rw    ] = round_tf32(acc[nt][1]+b1);
                Ts[(n  )*132 + rw + 8] = round_tf32(acc[nt][2]+b0);
                Ts[(n+1)*132 + rw + 8] = round_tf32(acc[nt][3]+b1);
            }
            __syncthreads();
            #pragma unroll
            for (int l2 = 0; l2 < 8; ++l2) {
                const int idx = tid + l2*256;
                const int row = idx >> 5, c4 = idx & 31;
                const float4 f = *(const float4*)(Ts + row*132 + c4*4);
                *(float4*)(outv + ((size_t)(bb*NH + h)*64 + row)*SEQ + s0 + c4*4) = f;
            }
        }
    }
}

// =====================================================================
// Kernel 1b: mask -> bitfield
// =====================================================================
__global__ void maskbits_kernel(const int* __restrict__ mask)
{
    const int gw = (blockIdx.x * 256 + threadIdx.x) >> 5;
    const int lane = threadIdx.x & 31;
    const int4 m = ((const int4*)mask)[(size_t)gw*32 + lane];
    u32 nib = (m.x ? 1u : 0u) | (m.y ? 2u : 0u) | (m.z ? 4u : 0u) | (m.w ? 8u : 0u);
    u32 val = nib << ((lane & 7) * 4);
    val |= __shfl_xor_sync(0xffffffffu, val, 1);
    val |= __shfl_xor_sync(0xffffffffu, val, 2);
    val |= __shfl_xor_sync(0xffffffffu, val, 4);
    if ((lane & 7) == 0) g_mbits[(size_t)gw*4 + (lane >> 3)] = val;
}

// =====================================================================
// Kernel 2: tf32 mma.sync flash attention, 2 CTAs/SM.
// Q frags re-loaded per iter via ldmatrix (regs<=128). S tile halved.
// Row sums via "ones" rows (64..71) appended to V tile.
// =====================================================================
#define SMB_K0 34816
#define SMB_K1 52224
#define SMB_V0 69632            // 72 rows x 68 floats = 19584 B
#define SMB_V1 89216
#define AT_SMEM 108800

__device__ __forceinline__ void load_kv_async(u32 smem_base, int st, int bh, int kt, int tid)
{
    const u32 kbase = smem_base + (st ? SMB_K1 : SMB_K0);
    const u32 vbase = smem_base + (st ? SMB_V1 : SMB_V0);
    const float4* kg = (const float4*)g_k + ((size_t)bh*SEQ + kt*64)*16;
    const float4* vg = (const float4*)g_v + (size_t)bh*64*(SEQ/4) + kt*16;
    #pragma unroll
    for (int l = 0; l < 4; ++l) {
        const int i = tid + l*256;
        const int row = i >> 4, c4 = i & 15;
        cpa16(kbase + (u32)(row*68 + c4*4)*4, kg + i);
        cpa16(vbase + (u32)(row*68 + c4*4)*4, vg + (size_t)row*(SEQ/4) + c4);
    }
}

__global__ __launch_bounds__(256, 2)
void attn_mma()
{
    extern __shared__ float smf[];
    const u32 smem_base = smem_u32(smf);
    const int tid = threadIdx.x;
    const int wid = tid >> 5, lane = tid & 31;
    const int r = lane >> 2, t = lane & 3;
    const int bh = blockIdx.y, b = bh >> 4, h = bh & 15;
    const int q0 = blockIdx.x * 128;

    {
        const float4* qg = (const float4*)g_q + ((size_t)bh*SEQ + q0)*16;
        #pragma unroll
        for (int l = 0; l < 8; ++l) {
            const int i = tid + l*256;
            const int row = i >> 4, c4 = i & 15;
            cpa16(smem_base + (u32)(row*68 + c4*4)*4, qg + i);
        }
        load_kv_async(smem_base, 0, bh, 0, tid);
        CPA_COMMIT();
        // ones rows 64..71 in both V stages (row 64 = 1.0 over s=0..63)
        for (int idx = tid; idx < 2*8*68; idx += 256) {
            const int stg = idx / (8*68);
            const int rr = (idx / 68) & 7;
            const int cc = idx % 68;
            smf[(stg ? SMB_V1 : SMB_V0)/4 + (64 + rr)*68 + cc] =
                (rr == 0 && cc < 64) ? 1.0f : 0.f;
        }
        CPA_WAIT0();
        __syncthreads();
    }

    // lane offsets: A-frag (a0,a1,a2,a3): +8rows for lanes 8-15, +16B for lanes>=16
    const u32 a_off = (u32)((lane & 7)*272 + ((lane >> 3) & 1)*2176 + ((lane >> 4) & 1)*16);
    // B-frag (f0=rows0-7/k0-3, f1=rows0-7/k4-7, f2=rows8-15/k0-3, f3=rows8-15/k4-7)
    const u32 b_off = (u32)((lane & 7)*272 + ((lane >> 4) & 1)*2176 + ((lane >> 3) & 1)*16);
    // x2 ones-frag: lanes 0-7 rows, lanes 8-15 +16B
    const u32 o_off = (u32)((lane & 7)*272 + ((lane >> 3) & 1)*16);
    const u32 qb = smem_base + (u32)wid*4352 + a_off;

    const int r1g = q0 + wid*16 + r;
    const u32* m1 = g_mbits + ((size_t)(b*SEQ + r1g)) * 64;
    const u32* m2 = m1 + 8*64;
    const int src1 = (lane & ~3) | (t >> 1);
    const int src2 = src1 | 2;
    const bool odd = (t & 1);

    float oacc[8][4];
    #pragma unroll
    for (int i = 0; i < 8; ++i)
        #pragma unroll
        for (int j = 0; j < 4; ++j) oacc[i][j] = 0.f;
    float ol[4] = {0.f, 0.f, 0.f, 0.f};

    #pragma unroll 1
    for (int kt = 0; kt < 32; ++kt) {
        const int st = kt & 1;
        __syncthreads();
        if (kt < 31) { load_kv_async(smem_base, st^1, bh, kt+1, tid); CPA_COMMIT(); CPA_WAIT1(); }
        else CPA_WAIT0();
        __syncthreads();

        const u32 kb    = smem_base + (st ? SMB_K1 : SMB_K0) + b_off;
        const u32 vb    = smem_base + (st ? SMB_V1 : SMB_V0) + b_off;
        const u32 vones = smem_base + (st ? SMB_V1 : SMB_V0) + 64*272 + o_off;

        #pragma unroll
        for (int half = 0; half < 2; ++half) {
            // ---- S half: 4 n-tiles of 8 columns ----
            float sa[4][4];
            #pragma unroll
            for (int i = 0; i < 4; ++i)
                #pragma unroll
                for (int j = 0; j < 4; ++j) sa[i][j] = 0.f;
            #pragma unroll
            for (int kk = 0; kk < 8; ++kk) {
                u32 aa[4];
                ldsm4(aa[0], aa[1], aa[2], aa[3], qb + kk*32);
                #pragma unroll
                for (int ntp = 0; ntp < 2; ++ntp) {
                    u32 f0, f1, f2, f3;
                    ldsm4(f0, f1, f2, f3, kb + (u32)((half*2 + ntp)*4352 + kk*32));
                    mma_tf32(sa[2*ntp    ], aa, f0, f1);
                    mma_tf32(sa[2*ntp + 1], aa, f2, f3);
                }
            }

            // ---- masked softmax (Q pre-scaled; no max pass) ----
            const u32 w1 = m1[kt*2 + half];
            const u32 w2 = m2[kt*2 + half];
            #pragma unroll
            for (int nt = 0; nt < 4; ++nt) {
                const int sh = nt*8 + 2*t;
                sa[nt][0] = ((w1 >> (sh  )) & 1u) ? ex2f(sa[nt][0]) : 0.f;
                sa[nt][1] = ((w1 >> (sh+1)) & 1u) ? ex2f(sa[nt][1]) : 0.f;
                sa[nt][2] = ((w2 >> (sh  )) & 1u) ? ex2f(sa[nt][2]) : 0.f;
                sa[nt][3] = ((w2 >> (sh+1)) & 1u) ? ex2f(sa[nt][3]) : 0.f;
            }

            // ---- PV half + row-sum via ones-tile ----
            #pragma unroll
            for (int jl = 0; jl < 4; ++jl) {
                const float x0 = __shfl_sync(0xffffffffu, sa[jl][0], src1);
                const float x1 = __shfl_sync(0xffffffffu, sa[jl][1], src1);
                const float x2 = __shfl_sync(0xffffffffu, sa[jl][2], src1);
                const float x3 = __shfl_sync(0xffffffffu, sa[jl][3], src1);
                const float y0 = __shfl_sync(0xffffffffu, sa[jl][0], src2);
                const float y1 = __shfl_sync(0xffffffffu, sa[jl][1], src2);
                const float y2 = __shfl_sync(0xffffffffu, sa[jl][2], src2);
                const float y3 = __shfl_sync(0xffffffffu, sa[jl][3], src2);
                u32 pa[4];
                pa[0] = __float_as_uint(odd ? x1 : x0);
                pa[1] = __float_as_uint(odd ? x3 : x2);
                pa[2] = __float_as_uint(odd ? y1 : y0);
                pa[3] = __float_as_uint(odd ? y3 : y2);
                const u32 colb = (u32)(half*128 + jl*32);
                #pragma unroll
                for (int dnp = 0; dnp < 4; ++dnp) {
                    u32 f0, f1, f2, f3;
                    ldsm4(f0, f1, f2, f3, vb + dnp*4352 + colb);
                    mma_tf32(oacc[2*dnp    ], pa, f0, f1);
                    mma_tf32(oacc[2*dnp + 1], pa, f2, f3);
                }
                u32 g0, g1;
                ldsm2(g0, g1, vones + colb);
                mma_tf32(ol, pa, g0, g1);
            }
        }
    }

    // ---- epilogue: l from ones-column (col 0 lives at t==0), write O/l hi+lo ----
    const float l1 = __shfl_sync(0xffffffffu, ol[0], lane & ~3);
    const float l2 = __shfl_sync(0xffffffffu, ol[2], lane & ~3);
    const float inv1 = 1.0f / l1;
    const float inv2 = 1.0f / l2;
    const size_t off1 = ((size_t)(b*SEQ + r1g    ))*DMODEL + h*64 + 2*t;
    const size_t off2 = ((size_t)(b*SEQ + r1g + 8))*DMODEL + h*64 + 2*t;
    #pragma unroll
    for (int dn = 0; dn < 8; ++dn) {
        const float v0 = oacc[dn][0]*inv1, v1 = oacc[dn][1]*inv1;
        const float v2 = oacc[dn][2]*inv2, v3 = oacc[dn][3]*inv2;
        const float h0 = round_tf32(v0), h1 = round_tf32(v1);
        const float h2 = round_tf32(v2), h3 = round_tf32(v3);
        *(float2*)(g_aoh + off1 + dn*8) = make_float2(h0, h1);
        *(float2*)(g_aol + off1 + dn*8) = make_float2(round_tf32(v0 - h0), round_tf32(v1 - h1));
        *(float2*)(g_aoh + off2 + dn*8) = make_float2(h2, h3);
        *(float2*)(g_aol + off2 + dn*8) = make_float2(round_tf32(v2 - h2), round_tf32(v3 - h3));
    }
}

// =====================================================================
// Kernel 3: output projection, 3xTF32 mma.sync (unchanged).
// =====================================================================
#define O_TILEB  18432
#define O_STAGEB (4*O_TILEB)
#define OPM_SMEM (2*O_STAGEB)

__device__ __forceinline__ void op_load(u32 smem_base, int st, int row0, int col0, int kt, int tid)
{
    const u32 sbase = smem_base + (u32)st*O_STAGEB;
    #pragma unroll
    for (int l = 0; l < 4; ++l) {
        const int i = tid + l*256;
        const int row = i >> 3, c4 = (i & 7)*4;
        const u32 off = (u32)(row*36 + c4)*4;
        const size_t ga = (size_t)(row0 + row)*DMODEL + kt*32 + c4;
        const size_t gb = (size_t)(col0 + row)*DMODEL + kt*32 + c4;
        cpa16(sbase             + off, g_aoh + ga);
        cpa16(sbase + O_TILEB   + off, g_aol + ga);
        cpa16(sbase + 2*O_TILEB + off, g_woh + gb);
        cpa16(sbase + 3*O_TILEB + off, g_wol + gb);
    }
}

__global__ __launch_bounds__(256)
void outproj_mma(const float* __restrict__ bo, float* __restrict__ out)
{
    extern __shared__ float smf[];
    const u32 smem_base = smem_u32(smf);
    const int tid = threadIdx.x;
    const int wid = tid >> 5, lane = tid & 31;
    const int r = lane >> 2, t = lane & 3;
    const int row0 = blockIdx.x * 128;
    const int col0 = blockIdx.y * 128;
    const int rw = wid*16 + r;

    op_load(smem_base, 0, row0, col0, 0, tid);
    CPA_COMMIT();

    float acc[16][4];
    #pragma unroll
    for (int i = 0; i < 16; ++i)
        #pragma unroll
        for (int j = 0; j < 4; ++j) acc[i][j] = 0.f;

    #pragma unroll 1
    for (int kt = 0; kt < 32; ++kt) {
        const int st = kt & 1;
        __syncthreads();
        if (kt < 31) { op_load(smem_base, st^1, row0, col0, kt+1, tid); CPA_COMMIT(); CPA_WAIT1(); }
        else CPA_WAIT0();
        __syncthreads();

        const float* Ah = smf + (size_t)st*O_STAGEB/4;
        const float* Al = Ah + O_TILEB/4;
        const float* Bh = Al + O_TILEB/4;
        const float* Bl = Bh + O_TILEB/4;

        #pragma unroll
        for (int kk = 0; kk < 4; ++kk) {
            const int ab = rw*36 + kk*8 + t;
            u32 ah[4], al[4];
            ah[0] = __float_as_uint(Ah[ab        ]);
            ah[1] = __float_as_uint(Ah[ab + 8*36 ]);
            ah[2] = __float_as_uint(Ah[ab + 4    ]);
            ah[3] = __float_as_uint(Ah[ab + 8*36 + 4]);
            al[0] = __float_as_uint(Al[ab        ]);
            al[1] = __float_as_uint(Al[ab + 8*36 ]);
            al[2] = __float_as_uint(Al[ab + 4    ]);
            al[3] = __float_as_uint(Al[ab + 8*36 + 4]);
            #pragma unroll
            for (int nt = 0; nt < 16; ++nt) {
                const int bb = (nt*8 + r)*36 + kk*8 + t;
                const u32 bh0 = __float_as_uint(Bh[bb    ]);
                const u32 bh1 = __float_as_uint(Bh[bb + 4]);
                const u32 bl0 = __float_as_uint(Bl[bb    ]);
                const u32 bl1 = __float_as_uint(Bl[bb + 4]);
                mma_tf32(acc[nt], ah, bh0, bh1);
                mma_tf32(acc[nt], ah, bl0, bl1);
                mma_tf32(acc[nt], al, bh0, bh1);
            }
        }
    }

    const int r1 = row0 + rw, r2 = r1 + 8;
    #pragma unroll
    for (int nt = 0; nt < 16; ++nt) {
        const int n = col0 + nt*8 + 2*t;
        const float b0 = bo[n], b1 = bo[n+1];
        *(float2*)(out + (size_t)r1*DMODEL + n) = make_float2(acc[nt][0] + b0, acc[nt][1] + b1);
        *(float2*)(out + (size_t)r2*DMODEL + n) = make_float2(acc[nt][2] + b0, acc[nt][3] + b1);
    }
}

// =====================================================================
// launch
// =====================================================================
extern "C" void kernel_launch(void* const* d_in, const int* in_sizes, int n_in,
                              void* d_out, int out_size)
{
    const float* values = (const float*)d_in[0];
    const float* keys   = (const float*)d_in[1];
    const float* query  = (const float*)d_in[2];
    const int*   mask   = (const int*)  d_in[3];
    const float* Wq     = (const float*)d_in[4];
    const float* bq     = (const float*)d_in[5];
    const float* Wk     = (const float*)d_in[6];
    const float* bk     = (const float*)d_in[7];
    const float* Wv     = (const float*)d_in[8];
    const float* bv     = (const float*)d_in[9];
    const float* Wo     = (const float*)d_in[10];
    const float* bo     = (const float*)d_in[11];
    float* out = (float*)d_out;

    cudaFuncSetAttribute(proj_mma,    cudaFuncAttributeMaxDynamicSharedMemorySize, PJ_SMEM);
    cudaFuncSetAttribute(attn_mma,    cudaFuncAttributeMaxDynamicSharedMemorySize, AT_SMEM);
    cudaFuncSetAttribute(outproj_mma, cudaFuncAttributeMaxDynamicSharedMemorySize, OPM_SMEM);

    void *pq, *pk, *pv;
    cudaGetSymbolAddress(&pq, g_q);
    cudaGetSymbolAddress(&pk, g_k);
    cudaGetSymbolAddress(&pv, g_v);

    wsplit_kernel<<<DMODEL*DMODEL/4/256, 256>>>(Wo);

    proj_mma<<<dim3(NTOK/128, 1, 3), 256, PJ_SMEM>>>(
        query, keys, values, Wq, bq, Wk, bk, Wv, bv,
        (float*)pq, (float*)pk, (float*)pv);

    maskbits_kernel<<<(BATCH*SEQ*SEQ/4)/256, 256>>>(mask);

    attn_mma<<<dim3(SEQ/128, BATCH*NH), 256, AT_SMEM>>>();

    outproj_mma<<<dim3(NTOK/128, DMODEL/128), 256, OPM_SMEM>>>(bo, out);
}

// round 12
// speedup vs baseline: 1.0263x; 1.0263x over previous
#include <cuda_runtime.h>
#include <cstdint>

#define BATCH   2
#define SEQ     2048
#define DMODEL  1024
#define NH      16
#define HD      64
#define NTOK    (BATCH*SEQ)

typedef unsigned long long ull;
typedef unsigned int u32;

#define SOFTMAX_C 0.045084220027f   // (1/32) * log2(e)

// ---------------- scratch (static device globals: allocation-free) ----------------
__device__ float g_q  [BATCH*NH*SEQ*HD];   // [bh][s][d]  (pre-scaled by SOFTMAX_C)
__device__ float g_k  [BATCH*NH*SEQ*HD];   // [bh][s][d]
__device__ float g_v  [BATCH*NH*HD*SEQ];   // [bh][d][s]
__device__ float g_aoh[NTOK*DMODEL];
__device__ float g_aol[NTOK*DMODEL];
__device__ float g_woh[DMODEL*DMODEL];
__device__ float g_wol[DMODEL*DMODEL];
__device__ u32   g_mbits[BATCH*SEQ*(SEQ/32)];

// ---------------- helpers ----------------
__device__ __forceinline__ float ex2f(float x){
    float y; asm("ex2.approx.ftz.f32 %0,%1;" : "=f"(y) : "f"(x)); return y;
}
__device__ __forceinline__ u32 cvt_tf32(float x){
    u32 y; asm("cvt.rna.tf32.f32 %0,%1;" : "=r"(y) : "f"(x)); return y;
}
__device__ __forceinline__ float round_tf32(float x){
    return __uint_as_float(cvt_tf32(x));
}
__device__ __forceinline__ void cpa16(u32 dst, const void* src){
    asm volatile("cp.async.cg.shared.global [%0], [%1], 16;" :: "r"(dst), "l"(src));
}
#define CPA_COMMIT() asm volatile("cp.async.commit_group;" ::: "memory")
#define CPA_WAIT0()  asm volatile("cp.async.wait_group 0;" ::: "memory")
#define CPA_WAIT1()  asm volatile("cp.async.wait_group 1;" ::: "memory")

__device__ __forceinline__ u32 smem_u32(const void* p){
    u32 a; asm("{ .reg .u64 t; cvta.to.shared.u64 t, %1; cvt.u32.u64 %0, t; }" : "=r"(a) : "l"(p));
    return a;
}
// mma.sync m16n8k8 tf32
__device__ __forceinline__ void mma_tf32(float* d, const u32* a, u32 b0, u32 b1){
    asm volatile("mma.sync.aligned.m16n8k8.row.col.f32.tf32.tf32.f32 "
        "{%0,%1,%2,%3},{%4,%5,%6,%7},{%8,%9},{%0,%1,%2,%3};"
        : "+f"(d[0]), "+f"(d[1]), "+f"(d[2]), "+f"(d[3])
        : "r"(a[0]), "r"(a[1]), "r"(a[2]), "r"(a[3]), "r"(b0), "r"(b1));
}
__device__ __forceinline__ void ldsm4(u32& r0, u32& r1, u32& r2, u32& r3, u32 addr){
    asm volatile("ldmatrix.sync.aligned.m8n8.x4.shared.b16 {%0,%1,%2,%3}, [%4];"
        : "=r"(r0), "=r"(r1), "=r"(r2), "=r"(r3) : "r"(addr));
}

// =====================================================================
// Kernel 0: split Wo into tf32 hi/lo
// =====================================================================
__global__ void wsplit_kernel(const float* __restrict__ W)
{
    const int i = blockIdx.x * 256 + threadIdx.x;
    const float4 w = ((const float4*)W)[i];
    float4 h, l;
    h.x = round_tf32(w.x); l.x = round_tf32(w.x - h.x);
    h.y = round_tf32(w.y); l.y = round_tf32(w.y - h.y);
    h.z = round_tf32(w.z); l.z = round_tf32(w.z - h.z);
    h.w = round_tf32(w.w); l.w = round_tf32(w.w - h.w);
    ((float4*)g_woh)[i] = h;
    ((float4*)g_wol)[i] = l;
}

// =====================================================================
// Kernel 1: QKV projection via tf32 mma. grid (NTOK/128, 1, 3).
// Q output pre-scaled by SOFTMAX_C. V written d-major.
// =====================================================================
#define PJ_WST 0
#define PJ_BS  17408
#define PJ_X0  17664
#define PJ_X1  52480
#define PJ_SMEM 87296

__device__ __forceinline__ void pj_load_x(u32 xb, const float* __restrict__ x,
                                          int q0, int hofs, int tid)
{
    #pragma unroll
    for (int l2 = 0; l2 < 8; ++l2) {
        const int i = tid + l2*256;
        const int row = i >> 4, c4 = i & 15;
        cpa16(xb + (u32)(row*68 + c4*4)*4,
              x + (size_t)(q0 + row)*DMODEL + hofs + c4*4);
    }
}

__global__ __launch_bounds__(256)
void proj_mma(const float* __restrict__ xq, const float* __restrict__ xk,
              const float* __restrict__ xv,
              const float* __restrict__ Wq_, const float* __restrict__ bq_,
              const float* __restrict__ Wk_, const float* __restrict__ bk_,
              const float* __restrict__ Wv_, const float* __restrict__ bv_,
              float* __restrict__ outq, float* __restrict__ outk,
              float* __restrict__ outv)
{
    extern __shared__ float smf[];
    const u32 smem_base = smem_u32(smf);
    const int tid = threadIdx.x;
    const int wid = tid >> 5, lane = tid & 31;
    const int r = lane >> 2, t = lane & 3;
    const int z = blockIdx.z;
    const float* x  = (z == 0) ? xq  : (z == 1) ? xk  : xv;
    const float* W  = (z == 0) ? Wq_ : (z == 1) ? Wk_ : Wv_;
    const float* bi = (z == 0) ? bq_ : (z == 1) ? bk_ : bv_;
    float* outg     = (z == 0) ? outq : (z == 1) ? outk : outv;
    const float qscale = (z == 0) ? SOFTMAX_C : 1.0f;
    const int q0 = blockIdx.x * 128;
    const int bb = q0 >> 11;
    const int s0 = q0 & (SEQ - 1);
    const int rw = wid*16 + r;

    for (int idx = tid; idx < 4096; idx += 256)
        smf[PJ_WST/4 + (idx >> 6)*68 + (idx & 63)] = W[idx];
    if (tid < 64) smf[PJ_BS/4 + tid] = bi[tid];

    pj_load_x(smem_base + PJ_X0, x, q0, 0, tid);
    CPA_COMMIT();
    __syncthreads();

    for (int h = 0; h < 16; ++h) {
        const int st = h & 1;
        CPA_WAIT0();
        __syncthreads();
        if (h < 15) {
            pj_load_x(smem_base + (st ? PJ_X0 : PJ_X1), x, q0, (h+1)*64, tid);
            CPA_COMMIT();
        }

        const float* Xs = smf + (st ? PJ_X1 : PJ_X0)/4;
        u32 af[8][4];
        #pragma unroll
        for (int kk = 0; kk < 8; ++kk) {
            af[kk][0] = __float_as_uint(Xs[(rw    )*68 + kk*8 + t    ]);
            af[kk][1] = __float_as_uint(Xs[(rw + 8)*68 + kk*8 + t    ]);
            af[kk][2] = __float_as_uint(Xs[(rw    )*68 + kk*8 + t + 4]);
            af[kk][3] = __float_as_uint(Xs[(rw + 8)*68 + kk*8 + t + 4]);
        }

        float acc[8][4];
        #pragma unroll
        for (int i = 0; i < 8; ++i)
            #pragma unroll
            for (int j = 0; j < 4; ++j) acc[i][j] = 0.f;

        const float* Wt = smf + PJ_WST/4;
        #pragma unroll
        for (int kk = 0; kk < 8; ++kk) {
            #pragma unroll
            for (int nt = 0; nt < 8; ++nt) {
                const u32 b0 = __float_as_uint(Wt[(nt*8 + r)*68 + kk*8 + t    ]);
                const u32 b1 = __float_as_uint(Wt[(nt*8 + r)*68 + kk*8 + t + 4]);
                mma_tf32(acc[nt], af[kk], b0, b1);
            }
        }

        const float* bsp = smf + PJ_BS/4;
        if (z < 2) {
            float* orow1 = outg + ((size_t)(bb*NH + h)*SEQ + s0 + rw    )*64;
            float* orow2 = outg + ((size_t)(bb*NH + h)*SEQ + s0 + rw + 8)*64;
            #pragma unroll
            for (int nt = 0; nt < 8; ++nt) {
                const int n = nt*8 + 2*t;
                const float b0 = bsp[n], b1 = bsp[n+1];
                *(float2*)(orow1 + n) = make_float2(round_tf32((acc[nt][0]+b0)*qscale),
                                                    round_tf32((acc[nt][1]+b1)*qscale));
                *(float2*)(orow2 + n) = make_float2(round_tf32((acc[nt][2]+b0)*qscale),
                                                    round_tf32((acc[nt][3]+b1)*qscale));
            }
        } else {
            __syncthreads();
            float* Ts = smf + (st ? PJ_X1 : PJ_X0)/4;
            #pragma unroll
            for (int nt = 0; nt < 8; ++nt) {
                const int n = nt*8 + 2*t;
                const float b0 = bsp[n], b1 = bsp[n+1];
                Ts[(n  )*132 + rw    ] = round_tf32(acc[nt][0]+b0);
                Ts[(n+1)*132 + rw    ] = round_tf32(acc[nt][1]+b1);
                Ts[(n  )*132 + rw + 8] = round_tf32(acc[nt][2]+b0);
                Ts[(n+1)*132 + rw + 8] = round_tf32(acc[nt][3]+b1);
            }
            __syncthreads();
            #pragma unroll
            for (int l2 = 0; l2 < 8; ++l2) {
                const int idx = tid + l2*256;
                const int row = idx >> 5, c4 = idx & 31;
                const float4 f = *(const float4*)(Ts + row*132 + c4*4);
                *(float4*)(outv + ((size_t)(bb*NH + h)*64 + row)*SEQ + s0 + c4*4) = f;
            }
        }
    }
}

// =====================================================================
// Kernel 1b: mask -> bitfield
// =====================================================================
__global__ void maskbits_kernel(const int* __restrict__ mask)
{
    const int gw = (blockIdx.x * 256 + threadIdx.x) >> 5;
    const int lane = threadIdx.x & 31;
    const int4 m = ((const int4*)mask)[(size_t)gw*32 + lane];
    u32 nib = (m.x ? 1u : 0u) | (m.y ? 2u : 0u) | (m.z ? 4u : 0u) | (m.w ? 8u : 0u);
    u32 val = nib << ((lane & 7) * 4);
    val |= __shfl_xor_sync(0xffffffffu, val, 1);
    val |= __shfl_xor_sync(0xffffffffu, val, 2);
    val |= __shfl_xor_sync(0xffffffffu, val, 4);
    if ((lane & 7) == 0) g_mbits[(size_t)gw*4 + (lane >> 3)] = val;
}

// =====================================================================
// Kernel 2: tf32 mma.sync flash attention, 2 CTAs/SM.
// Q register-resident (zero per-iter Q smem traffic), S tile halved
// (regs <= 128), scalar row sums of tf32-rounded P.
// =====================================================================
#define SMB_K0 34816
#define SMB_K1 52224
#define SMB_V0 69632
#define SMB_V1 87040
#define AT_SMEM 104448

__device__ __forceinline__ void load_kv_async(u32 smem_base, int st, int bh, int kt, int tid)
{
    const u32 kbase = smem_base + (st ? SMB_K1 : SMB_K0);
    const u32 vbase = smem_base + (st ? SMB_V1 : SMB_V0);
    const float4* kg = (const float4*)g_k + ((size_t)bh*SEQ + kt*64)*16;
    const float4* vg = (const float4*)g_v + (size_t)bh*64*(SEQ/4) + kt*16;
    #pragma unroll
    for (int l = 0; l < 4; ++l) {
        const int i = tid + l*256;
        const int row = i >> 4, c4 = i & 15;
        cpa16(kbase + (u32)(row*68 + c4*4)*4, kg + i);
        cpa16(vbase + (u32)(row*68 + c4*4)*4, vg + (size_t)row*(SEQ/4) + c4);
    }
}

__global__ __launch_bounds__(256, 2)
void attn_mma()
{
    extern __shared__ float smf[];
    const u32 smem_base = smem_u32(smf);
    const int tid = threadIdx.x;
    const int wid = tid >> 5, lane = tid & 31;
    const int r = lane >> 2, t = lane & 3;
    const int bh = blockIdx.y, b = bh >> 4, h = bh & 15;
    const int q0 = blockIdx.x * 128;

    {
        const float4* qg = (const float4*)g_q + ((size_t)bh*SEQ + q0)*16;
        #pragma unroll
        for (int l = 0; l < 8; ++l) {
            const int i = tid + l*256;
            const int row = i >> 4, c4 = i & 15;
            cpa16(smem_base + (u32)(row*68 + c4*4)*4, qg + i);
        }
        load_kv_async(smem_base, 0, bh, 0, tid);
        CPA_COMMIT();
        CPA_WAIT0();
        __syncthreads();
    }

    // Q fragments register-resident (M=16 rows per warp)
    u32 qa[8][4];
    {
        const float* Qs = smf;
        const int rw = wid*16 + r;
        #pragma unroll
        for (int kk = 0; kk < 8; ++kk) {
            qa[kk][0] = __float_as_uint(Qs[(rw    )*68 + kk*8 + t    ]);
            qa[kk][1] = __float_as_uint(Qs[(rw + 8)*68 + kk*8 + t    ]);
            qa[kk][2] = __float_as_uint(Qs[(rw    )*68 + kk*8 + t + 4]);
            qa[kk][3] = __float_as_uint(Qs[(rw + 8)*68 + kk*8 + t + 4]);
        }
    }

    // B-frag ldmatrix lane offset
    const u32 b_off = (u32)((lane & 7)*272 + ((lane >> 4) & 1)*2176 + ((lane >> 3) & 1)*16);

    const int r1g = q0 + wid*16 + r;
    const u32* m1 = g_mbits + ((size_t)(b*SEQ + r1g)) * 64;
    const u32* m2 = m1 + 8*64;
    const int src1 = (lane & ~3) | (t >> 1);
    const int src2 = src1 | 2;
    const bool odd = (t & 1);

    float oacc[8][4];
    #pragma unroll
    for (int i = 0; i < 8; ++i)
        #pragma unroll
        for (int j = 0; j < 4; ++j) oacc[i][j] = 0.f;
    float ls1 = 0.f, ls2 = 0.f;

    #pragma unroll 1
    for (int kt = 0; kt < 32; ++kt) {
        const int st = kt & 1;
        __syncthreads();
        if (kt < 31) { load_kv_async(smem_base, st^1, bh, kt+1, tid); CPA_COMMIT(); CPA_WAIT1(); }
        else CPA_WAIT0();
        __syncthreads();

        const u32 kb = smem_base + (st ? SMB_K1 : SMB_K0) + b_off;
        const u32 vb = smem_base + (st ? SMB_V1 : SMB_V0) + b_off;

        #pragma unroll
        for (int half = 0; half < 2; ++half) {
            // ---- S half: 32 s-columns ----
            float sa[4][4];
            #pragma unroll
            for (int i = 0; i < 4; ++i)
                #pragma unroll
                for (int j = 0; j < 4; ++j) sa[i][j] = 0.f;
            #pragma unroll
            for (int kk = 0; kk < 8; ++kk) {
                #pragma unroll
                for (int ntp = 0; ntp < 2; ++ntp) {
                    u32 f0, f1, f2, f3;
                    ldsm4(f0, f1, f2, f3, kb + (u32)((half*2 + ntp)*4352 + kk*32));
                    mma_tf32(sa[2*ntp    ], qa[kk], f0, f1);
                    mma_tf32(sa[2*ntp + 1], qa[kk], f2, f3);
                }
            }

            // ---- masked softmax (Q pre-scaled); tf32-round P, sum rounded P ----
            const u32 w1 = m1[kt*2 + half];
            const u32 w2 = m2[kt*2 + half];
            #pragma unroll
            for (int nt = 0; nt < 4; ++nt) {
                const int sh = nt*8 + 2*t;
                float p;
                p = ((w1 >> (sh  )) & 1u) ? round_tf32(ex2f(sa[nt][0])) : 0.f; sa[nt][0] = p; ls1 += p;
                p = ((w1 >> (sh+1)) & 1u) ? round_tf32(ex2f(sa[nt][1])) : 0.f; sa[nt][1] = p; ls1 += p;
                p = ((w2 >> (sh  )) & 1u) ? round_tf32(ex2f(sa[nt][2])) : 0.f; sa[nt][2] = p; ls2 += p;
                p = ((w2 >> (sh+1)) & 1u) ? round_tf32(ex2f(sa[nt][3])) : 0.f; sa[nt][3] = p; ls2 += p;
            }

            // ---- PV half ----
            #pragma unroll
            for (int jl = 0; jl < 4; ++jl) {
                const float x0 = __shfl_sync(0xffffffffu, sa[jl][0], src1);
                const float x1 = __shfl_sync(0xffffffffu, sa[jl][1], src1);
                const float x2 = __shfl_sync(0xffffffffu, sa[jl][2], src1);
                const float x3 = __shfl_sync(0xffffffffu, sa[jl][3], src1);
                const float y0 = __shfl_sync(0xffffffffu, sa[jl][0], src2);
                const float y1 = __shfl_sync(0xffffffffu, sa[jl][1], src2);
                const float y2 = __shfl_sync(0xffffffffu, sa[jl][2], src2);
                const float y3 = __shfl_sync(0xffffffffu, sa[jl][3], src2);
                u32 pa[4];
                pa[0] = __float_as_uint(odd ? x1 : x0);
                pa[1] = __float_as_uint(odd ? x3 : x2);
                pa[2] = __float_as_uint(odd ? y1 : y0);
                pa[3] = __float_as_uint(odd ? y3 : y2);
                const u32 colb = (u32)(half*128 + jl*32);
                #pragma unroll
                for (int dnp = 0; dnp < 4; ++dnp) {
                    u32 f0, f1, f2, f3;
                    ldsm4(f0, f1, f2, f3, vb + dnp*4352 + colb);
                    mma_tf32(oacc[2*dnp    ], pa, f0, f1);
                    mma_tf32(oacc[2*dnp + 1], pa, f2, f3);
                }
            }
        }
    }

    // ---- epilogue: quad-reduce row sums, write O/l split into tf32 hi+lo ----
    ls1 += __shfl_xor_sync(0xffffffffu, ls1, 1);
    ls1 += __shfl_xor_sync(0xffffffffu, ls1, 2);
    ls2 += __shfl_xor_sync(0xffffffffu, ls2, 1);
    ls2 += __shfl_xor_sync(0xffffffffu, ls2, 2);
    const float inv1 = 1.0f / ls1;
    const float inv2 = 1.0f / ls2;
    const size_t off1 = ((size_t)(b*SEQ + r1g    ))*DMODEL + h*64 + 2*t;
    const size_t off2 = ((size_t)(b*SEQ + r1g + 8))*DMODEL + h*64 + 2*t;
    #pragma unroll
    for (int dn = 0; dn < 8; ++dn) {
        const float v0 = oacc[dn][0]*inv1, v1 = oacc[dn][1]*inv1;
        const float v2 = oacc[dn][2]*inv2, v3 = oacc[dn][3]*inv2;
        const float h0 = round_tf32(v0), h1 = round_tf32(v1);
        const float h2 = round_tf32(v2), h3 = round_tf32(v3);
        *(float2*)(g_aoh + off1 + dn*8) = make_float2(h0, h1);
        *(float2*)(g_aol + off1 + dn*8) = make_float2(round_tf32(v0 - h0), round_tf32(v1 - h1));
        *(float2*)(g_aoh + off2 + dn*8) = make_float2(h2, h3);
        *(float2*)(g_aol + off2 + dn*8) = make_float2(round_tf32(v2 - h2), round_tf32(v3 - h3));
    }
}

// =====================================================================
// Kernel 3: output projection, 3xTF32 mma.sync (unchanged).
// =====================================================================
#define O_TILEB  18432
#define O_STAGEB (4*O_TILEB)
#define OPM_SMEM (2*O_STAGEB)

__device__ __forceinline__ void op_load(u32 smem_base, int st, int row0, int col0, int kt, int tid)
{
    const u32 sbase = smem_base + (u32)st*O_STAGEB;
    #pragma unroll
    for (int l = 0; l < 4; ++l) {
        const int i = tid + l*256;
        const int row = i >> 3, c4 = (i & 7)*4;
        const u32 off = (u32)(row*36 + c4)*4;
        const size_t ga = (size_t)(row0 + row)*DMODEL + kt*32 + c4;
        const size_t gb = (size_t)(col0 + row)*DMODEL + kt*32 + c4;
        cpa16(sbase             + off, g_aoh + ga);
        cpa16(sbase + O_TILEB   + off, g_aol + ga);
        cpa16(sbase + 2*O_TILEB + off, g_woh + gb);
        cpa16(sbase + 3*O_TILEB + off, g_wol + gb);
    }
}

__global__ __launch_bounds__(256)
void outproj_mma(const float* __restrict__ bo, float* __restrict__ out)
{
    extern __shared__ float smf[];
    const u32 smem_base = smem_u32(smf);
    const int tid = threadIdx.x;
    const int wid = tid >> 5, lane = tid & 31;
    const int r = lane >> 2, t = lane & 3;
    const int row0 = blockIdx.x * 128;
    const int col0 = blockIdx.y * 128;
    const int rw = wid*16 + r;

    op_load(smem_base, 0, row0, col0, 0, tid);
    CPA_COMMIT();

    float acc[16][4];
    #pragma unroll
    for (int i = 0; i < 16; ++i)
        #pragma unroll
        for (int j = 0; j < 4; ++j) acc[i][j] = 0.f;

    #pragma unroll 1
    for (int kt = 0; kt < 32; ++kt) {
        const int st = kt & 1;
        __syncthreads();
        if (kt < 31) { op_load(smem_base, st^1, row0, col0, kt+1, tid); CPA_COMMIT(); CPA_WAIT1(); }
        else CPA_WAIT0();
        __syncthreads();

        const float* Ah = smf + (size_t)st*O_STAGEB/4;
        const float* Al = Ah + O_TILEB/4;
        const float* Bh = Al + O_TILEB/4;
        const float* Bl = Bh + O_TILEB/4;

        #pragma unroll
        for (int kk = 0; kk < 4; ++kk) {
            const int ab = rw*36 + kk*8 + t;
            u32 ah[4], al[4];
            ah[0] = __float_as_uint(Ah[ab        ]);
            ah[1] = __float_as_uint(Ah[ab + 8*36 ]);
            ah[2] = __float_as_uint(Ah[ab + 4    ]);
            ah[3] = __float_as_uint(Ah[ab + 8*36 + 4]);
            al[0] = __float_as_uint(Al[ab        ]);
            al[1] = __float_as_uint(Al[ab + 8*36 ]);
            al[2] = __float_as_uint(Al[ab + 4    ]);
            al[3] = __float_as_uint(Al[ab + 8*36 + 4]);
            #pragma unroll
            for (int nt = 0; nt < 16; ++nt) {
                const int bb = (nt*8 + r)*36 + kk*8 + t;
                const u32 bh0 = __float_as_uint(Bh[bb    ]);
                const u32 bh1 = __float_as_uint(Bh[bb + 4]);
                const u32 bl0 = __float_as_uint(Bl[bb    ]);
                const u32 bl1 = __float_as_uint(Bl[bb + 4]);
                mma_tf32(acc[nt], ah, bh0, bh1);
                mma_tf32(acc[nt], ah, bl0, bl1);
                mma_tf32(acc[nt], al, bh0, bh1);
            }
        }
    }

    const int r1 = row0 + rw, r2 = r1 + 8;
    #pragma unroll
    for (int nt = 0; nt < 16; ++nt) {
        const int n = col0 + nt*8 + 2*t;
        const float b0 = bo[n], b1 = bo[n+1];
        *(float2*)(out + (size_t)r1*DMODEL + n) = make_float2(acc[nt][0] + b0, acc[nt][1] + b1);
        *(float2*)(out + (size_t)r2*DMODEL + n) = make_float2(acc[nt][2] + b0, acc[nt][3] + b1);
    }
}

// =====================================================================
// launch
// =====================================================================
extern "C" void kernel_launch(void* const* d_in, const int* in_sizes, int n_in,
                              void* d_out, int out_size)
{
    const float* values = (const float*)d_in[0];
    const float* keys   = (const float*)d_in[1];
    const float* query  = (const float*)d_in[2];
    const int*   mask   = (const int*)  d_in[3];
    const float* Wq     = (const float*)d_in[4];
    const float* bq     = (const float*)d_in[5];
    const float* Wk     = (const float*)d_in[6];
    const float* bk     = (const float*)d_in[7];
    const float* Wv     = (const float*)d_in[8];
    const float* bv     = (const float*)d_in[9];
    const float* Wo     = (const float*)d_in[10];
    const float* bo     = (const float*)d_in[11];
    float* out = (float*)d_out;

    cudaFuncSetAttribute(proj_mma,    cudaFuncAttributeMaxDynamicSharedMemorySize, PJ_SMEM);
    cudaFuncSetAttribute(attn_mma,    cudaFuncAttributeMaxDynamicSharedMemorySize, AT_SMEM);
    cudaFuncSetAttribute(outproj_mma, cudaFuncAttributeMaxDynamicSharedMemorySize, OPM_SMEM);

    void *pq, *pk, *pv;
    cudaGetSymbolAddress(&pq, g_q);
    cudaGetSymbolAddress(&pk, g_k);
    cudaGetSymbolAddress(&pv, g_v);

    wsplit_kernel<<<DMODEL*DMODEL/4/256, 256>>>(Wo);

    proj_mma<<<dim3(NTOK/128, 1, 3), 256, PJ_SMEM>>>(
        query, keys, values, Wq, bq, Wk, bk, Wv, bv,
        (float*)pq, (float*)pk, (float*)pv);

    maskbits_kernel<<<(BATCH*SEQ*SEQ/4)/256, 256>>>(mask);

    attn_mma<<<dim3(SEQ/128, BATCH*NH), 256, AT_SMEM>>>();

    outproj_mma<<<dim3(NTOK/128, DMODEL/128), 256, OPM_SMEM>>>(bo, out);
}

// round 13
// speedup vs baseline: 1.0920x; 1.0640x over previous
#include <cuda_runtime.h>
#include <cstdint>

#define BATCH   2
#define SEQ     2048
#define DMODEL  1024
#define NH      16
#define HD      64
#define NTOK    (BATCH*SEQ)

typedef unsigned long long ull;
typedef unsigned int u32;

#define SOFTMAX_C 0.045084220027f   // (1/32) * log2(e)

// ---------------- scratch (static device globals: allocation-free) ----------------
// Tiled + swizzled layouts (written by proj_mma, bulk-copied by attn):
//  g_q: [bh][qt=16][tile 128x64]  tile = 32KB, off = row*64 + ((ch^(row&7))*4)+i
//  g_k: [bh][st=32][tile  64x64]  tile = 16KB, same formula
//  g_v: [bh][vt=32][tile d=64 x s=64] tile = 16KB (d-major), same formula
__device__ float g_q  [BATCH*NH*SEQ*HD];
__device__ float g_k  [BATCH*NH*SEQ*HD];
__device__ float g_v  [BATCH*NH*HD*SEQ];
__device__ float g_aoh[NTOK*DMODEL];
__device__ float g_aol[NTOK*DMODEL];
__device__ float g_woh[DMODEL*DMODEL];
__device__ float g_wol[DMODEL*DMODEL];
__device__ u32   g_mbits[BATCH*SEQ*(SEQ/32)];

// ---------------- helpers ----------------
__device__ __forceinline__ float ex2f(float x){
    float y; asm("ex2.approx.ftz.f32 %0,%1;" : "=f"(y) : "f"(x)); return y;
}
__device__ __forceinline__ u32 cvt_tf32(float x){
    u32 y; asm("cvt.rna.tf32.f32 %0,%1;" : "=r"(y) : "f"(x)); return y;
}
__device__ __forceinline__ float round_tf32(float x){
    return __uint_as_float(cvt_tf32(x));
}
__device__ __forceinline__ void cpa16(u32 dst, const void* src){
    asm volatile("cp.async.cg.shared.global [%0], [%1], 16;" :: "r"(dst), "l"(src));
}
#define CPA_COMMIT() asm volatile("cp.async.commit_group;" ::: "memory")
#define CPA_WAIT0()  asm volatile("cp.async.wait_group 0;" ::: "memory")
#define CPA_WAIT1()  asm volatile("cp.async.wait_group 1;" ::: "memory")

__device__ __forceinline__ u32 smem_u32(const void* p){
    u32 a; asm("{ .reg .u64 t; cvta.to.shared.u64 t, %1; cvt.u32.u64 %0, t; }" : "=r"(a) : "l"(p));
    return a;
}
// mma.sync m16n8k8 tf32
__device__ __forceinline__ void mma_tf32(float* d, const u32* a, u32 b0, u32 b1){
    asm volatile("mma.sync.aligned.m16n8k8.row.col.f32.tf32.tf32.f32 "
        "{%0,%1,%2,%3},{%4,%5,%6,%7},{%8,%9},{%0,%1,%2,%3};"
        : "+f"(d[0]), "+f"(d[1]), "+f"(d[2]), "+f"(d[3])
        : "r"(a[0]), "r"(a[1]), "r"(a[2]), "r"(a[3]), "r"(b0), "r"(b1));
}
__device__ __forceinline__ void ldsm4(u32& r0, u32& r1, u32& r2, u32& r3, u32 addr){
    asm volatile("ldmatrix.sync.aligned.m8n8.x4.shared.b16 {%0,%1,%2,%3}, [%4];"
        : "=r"(r0), "=r"(r1), "=r"(r2), "=r"(r3) : "r"(addr));
}

// ---------------- mbarrier + bulk copy ----------------
#define MBARRIER_INIT(addr, cnt) \
    asm volatile("mbarrier.init.shared.b64 [%0], %1;" :: "r"((u32)(addr)), "r"((u32)(cnt)) : "memory")
#define MBARRIER_EXPECT_TX(addr, bytes) \
    asm volatile("mbarrier.arrive.expect_tx.shared.b64 _, [%0], %1;" :: "r"((u32)(addr)), "r"((u32)(bytes)) : "memory")
#define FENCE_PROXY_ASYNC() asm volatile("fence.proxy.async.shared::cta;" ::: "memory")
#define MBARRIER_WAIT_PARITY(mbar, parity) do { \
    u32 _m = (u32)(mbar); u32 _p = (u32)(parity); u32 _done; \
    asm volatile("{\n\t.reg .pred p;\n\t" \
        "mbarrier.try_wait.parity.acquire.cta.shared::cta.b64 p, [%1], %2;\n\t" \
        "selp.b32 %0, 1, 0, p;\n\t}" : "=r"(_done) : "r"(_m), "r"(_p) : "memory"); \
    if (!_done) { \
        asm volatile("{\n\t.reg .pred P1;\n\t" \
            "WAIT_LOOP_%=:\n\t" \
            "mbarrier.try_wait.parity.acquire.cta.shared::cta.b64 P1, [%0], %1, 0x989680;\n\t" \
            "@P1 bra.uni WAIT_DONE_%=;\n\t" \
            "bra.uni WAIT_LOOP_%=;\n\t" \
            "WAIT_DONE_%=:\n\t}" :: "r"(_m), "r"(_p) : "memory"); \
    } } while(0)

__device__ __forceinline__ void cpbulk(u32 dst, const void* src, u32 bytes, u32 mbar){
    asm volatile("cp.async.bulk.shared::cluster.global.mbarrier::complete_tx::bytes "
                 "[%0], [%1], %2, [%3];"
                 :: "r"(dst), "l"(src), "r"(bytes), "r"(mbar) : "memory");
}

// =====================================================================
// Kernel 0: split Wo into tf32 hi/lo
// =====================================================================
__global__ void wsplit_kernel(const float* __restrict__ W)
{
    const int i = blockIdx.x * 256 + threadIdx.x;
    const float4 w = ((const float4*)W)[i];
    float4 h, l;
    h.x = round_tf32(w.x); l.x = round_tf32(w.x - h.x);
    h.y = round_tf32(w.y); l.y = round_tf32(w.y - h.y);
    h.z = round_tf32(w.z); l.z = round_tf32(w.z - h.z);
    h.w = round_tf32(w.w); l.w = round_tf32(w.w - h.w);
    ((float4*)g_woh)[i] = h;
    ((float4*)g_wol)[i] = l;
}

// =====================================================================
// Kernel 1: QKV projection via tf32 mma. grid (NTOK/128, 1, 3).
// Writes tiled+swizzled layouts. Q pre-scaled by SOFTMAX_C.
// =====================================================================
#define PJ_WST 0
#define PJ_BS  17408
#define PJ_X0  17664
#define PJ_X1  52480
#define PJ_SMEM 87296

__device__ __forceinline__ void pj_load_x(u32 xb, const float* __restrict__ x,
                                          int q0, int hofs, int tid)
{
    #pragma unroll
    for (int l2 = 0; l2 < 8; ++l2) {
        const int i = tid + l2*256;
        const int row = i >> 4, c4 = i & 15;
        cpa16(xb + (u32)(row*68 + c4*4)*4,
              x + (size_t)(q0 + row)*DMODEL + hofs + c4*4);
    }
}

__global__ __launch_bounds__(256)
void proj_mma(const float* __restrict__ xq, const float* __restrict__ xk,
              const float* __restrict__ xv,
              const float* __restrict__ Wq_, const float* __restrict__ bq_,
              const float* __restrict__ Wk_, const float* __restrict__ bk_,
              const float* __restrict__ Wv_, const float* __restrict__ bv_,
              float* __restrict__ outq, float* __restrict__ outk,
              float* __restrict__ outv)
{
    extern __shared__ float smf[];
    const u32 smem_base = smem_u32(smf);
    const int tid = threadIdx.x;
    const int wid = tid >> 5, lane = tid & 31;
    const int r = lane >> 2, t = lane & 3;
    const int z = blockIdx.z;
    const float* x  = (z == 0) ? xq  : (z == 1) ? xk  : xv;
    const float* W  = (z == 0) ? Wq_ : (z == 1) ? Wk_ : Wv_;
    const float* bi = (z == 0) ? bq_ : (z == 1) ? bk_ : bv_;
    float* outg     = (z == 0) ? outq : (z == 1) ? outk : outv;
    const float qscale = (z == 0) ? SOFTMAX_C : 1.0f;
    const int q0 = blockIdx.x * 128;
    const int bb = q0 >> 11;
    const int s0 = q0 & (SEQ - 1);
    const int rw = wid*16 + r;

    for (int idx = tid; idx < 4096; idx += 256)
        smf[PJ_WST/4 + (idx >> 6)*68 + (idx & 63)] = W[idx];
    if (tid < 64) smf[PJ_BS/4 + tid] = bi[tid];

    pj_load_x(smem_base + PJ_X0, x, q0, 0, tid);
    CPA_COMMIT();
    __syncthreads();

    for (int h = 0; h < 16; ++h) {
        const int st = h & 1;
        CPA_WAIT0();
        __syncthreads();
        if (h < 15) {
            pj_load_x(smem_base + (st ? PJ_X0 : PJ_X1), x, q0, (h+1)*64, tid);
            CPA_COMMIT();
        }

        const float* Xs = smf + (st ? PJ_X1 : PJ_X0)/4;
        u32 af[8][4];
        #pragma unroll
        for (int kk = 0; kk < 8; ++kk) {
            af[kk][0] = __float_as_uint(Xs[(rw    )*68 + kk*8 + t    ]);
            af[kk][1] = __float_as_uint(Xs[(rw + 8)*68 + kk*8 + t    ]);
            af[kk][2] = __float_as_uint(Xs[(rw    )*68 + kk*8 + t + 4]);
            af[kk][3] = __float_as_uint(Xs[(rw + 8)*68 + kk*8 + t + 4]);
        }

        float acc[8][4];
        #pragma unroll
        for (int i = 0; i < 8; ++i)
            #pragma unroll
            for (int j = 0; j < 4; ++j) acc[i][j] = 0.f;

        const float* Wt = smf + PJ_WST/4;
        #pragma unroll
        for (int kk = 0; kk < 8; ++kk) {
            #pragma unroll
            for (int nt = 0; nt < 8; ++nt) {
                const u32 b0 = __float_as_uint(Wt[(nt*8 + r)*68 + kk*8 + t    ]);
                const u32 b1 = __float_as_uint(Wt[(nt*8 + r)*68 + kk*8 + t + 4]);
                mma_tf32(acc[nt], af[kk], b0, b1);
            }
        }

        const float* bsp = smf + PJ_BS/4;
        const int xr = rw & 7;                    // (rw+8)&7 == rw&7
        if (z == 0) {
            // Q: tile [bh][qt][128x64] swizzled
            float* tb = outg + ((size_t)(bb*NH + h)*16 + (s0 >> 7))*8192;
            #pragma unroll
            for (int nt = 0; nt < 8; ++nt) {
                const int n = nt*8 + 2*t;
                const int ch = n >> 2, ii = n & 3;
                const int sw = ((ch ^ xr) * 4) + ii;
                const float b0 = bsp[n], b1 = bsp[n+1];
                *(float2*)(tb + (rw    )*64 + sw) =
                    make_float2(round_tf32((acc[nt][0]+b0)*qscale),
                                round_tf32((acc[nt][1]+b1)*qscale));
                *(float2*)(tb + (rw + 8)*64 + sw) =
                    make_float2(round_tf32((acc[nt][2]+b0)*qscale),
                                round_tf32((acc[nt][3]+b1)*qscale));
            }
        } else if (z == 1) {
            // K: tile [bh][st][64x64] swizzled (rw and rw+8 stay in same tile)
            float* tb = outg + ((size_t)(bb*NH + h)*32 + (s0 >> 6) + (rw >> 6))*4096;
            const int r64 = rw & 63;
            #pragma unroll
            for (int nt = 0; nt < 8; ++nt) {
                const int n = nt*8 + 2*t;
                const int ch = n >> 2, ii = n & 3;
                const int sw = ((ch ^ xr) * 4) + ii;
                const float b0 = bsp[n], b1 = bsp[n+1];
                *(float2*)(tb + (r64    )*64 + sw) =
                    make_float2(round_tf32(acc[nt][0]+b0), round_tf32(acc[nt][1]+b1));
                *(float2*)(tb + (r64 + 8)*64 + sw) =
                    make_float2(round_tf32(acc[nt][2]+b0), round_tf32(acc[nt][3]+b1));
            }
        } else {
            // V: transpose-stage then write d-major tiles [bh][vt][64x64] swizzled
            __syncthreads();
            float* Ts = smf + (st ? PJ_X1 : PJ_X0)/4;   // [d][tok] stride 132
            #pragma unroll
            for (int nt = 0; nt < 8; ++nt) {
                const int n = nt*8 + 2*t;
                const float b0 = bsp[n], b1 = bsp[n+1];
                Ts[(n  )*132 + rw    ] = round_tf32(acc[nt][0]+b0);
                Ts[(n+1)*132 + rw    ] = round_tf32(acc[nt][1]+b1);
                Ts[(n  )*132 + rw + 8] = round_tf32(acc[nt][2]+b0);
                Ts[(n+1)*132 + rw + 8] = round_tf32(acc[nt][3]+b1);
            }
            __syncthreads();
            #pragma unroll
            for (int l2 = 0; l2 < 8; ++l2) {
                const int idx = tid + l2*256;            // 0..2047 float4s
                const int row = idx >> 5, c4 = idx & 31; // row=d, c4 = s-chunk of 128 tokens
                const float4 f = *(const float4*)(Ts + row*132 + c4*4);
                const int vt = (s0 >> 6) + (c4 >> 4);
                const int ch = c4 & 15;
                float* vb2 = outv + ((size_t)(bb*NH + h)*32 + vt)*4096;
                *(float4*)(vb2 + row*64 + ((ch ^ (row & 7))*4)) = f;
            }
        }
    }
}

// =====================================================================
// Kernel 1b: mask -> bitfield
// =====================================================================
__global__ void maskbits_kernel(const int* __restrict__ mask)
{
    const int gw = (blockIdx.x * 256 + threadIdx.x) >> 5;
    const int lane = threadIdx.x & 31;
    const int4 m = ((const int4*)mask)[(size_t)gw*32 + lane];
    u32 nib = (m.x ? 1u : 0u) | (m.y ? 2u : 0u) | (m.z ? 4u : 0u) | (m.w ? 8u : 0u);
    u32 val = nib << ((lane & 7) * 4);
    val |= __shfl_xor_sync(0xffffffffu, val, 1);
    val |= __shfl_xor_sync(0xffffffffu, val, 2);
    val |= __shfl_xor_sync(0xffffffffu, val, 4);
    if ((lane & 7) == 0) g_mbits[(size_t)gw*4 + (lane >> 3)] = val;
}

// =====================================================================
// Kernel 2: tf32 mma.sync flash attention, 2 CTAs/SM.
// cp.async.bulk tile loads (2 instr/iter) + mbarrier double-buffer.
// Swizzled smem tiles, conflict-free ldmatrix, reg-resident Q.
// =====================================================================
#define SMB_Q  0
#define SMB_K0 32768
#define SMB_K1 49152
#define SMB_V0 65536
#define SMB_V1 81920
#define SMB_MB 98304
#define AT_SMEM 98432

__global__ __launch_bounds__(256, 2)
void attn_mma()
{
    extern __shared__ float smf[];
    const u32 smem_base = smem_u32(smf);
    const int tid = threadIdx.x;
    const int wid = tid >> 5, lane = tid & 31;
    const int r = lane >> 2, t = lane & 3;
    const int bh = blockIdx.y, b = bh >> 4, h = bh & 15;
    const int q0 = blockIdx.x * 128;
    const u32 mb0 = smem_base + SMB_MB;
    const u32 mb1 = smem_base + SMB_MB + 8;

    if (tid == 0) { MBARRIER_INIT(mb0, 1); MBARRIER_INIT(mb1, 1); FENCE_PROXY_ASYNC(); }
    __syncthreads();
    if (tid == 0) {
        MBARRIER_EXPECT_TX(mb0, 65536);
        cpbulk(smem_base + SMB_Q,  g_q + ((size_t)bh*16 + (q0 >> 7))*8192, 32768, mb0);
        cpbulk(smem_base + SMB_K0, g_k + ((size_t)bh*32)*4096, 16384, mb0);
        cpbulk(smem_base + SMB_V0, g_v + ((size_t)bh*32)*4096, 16384, mb0);
    }
    int ph0 = 0, ph1 = 0;
    MBARRIER_WAIT_PARITY(mb0, ph0); ph0 = 1;

    // ---- Q fragments, register-resident, via swizzled ldsm ----
    const int r7 = lane & 7;
    u32 qa[8][4];
    {
        const u32 rowa = (u32)(wid*16 + r7 + ((lane >> 3) & 1)*8);
        const u32 hba = (u32)((lane >> 4) & 1);
        #pragma unroll
        for (int kk = 0; kk < 8; ++kk) {
            const u32 addr = smem_base + SMB_Q + rowa*256 + ((((u32)(kk<<1) + hba) ^ (u32)r7) << 4);
            ldsm4(qa[kk][0], qa[kk][1], qa[kk][2], qa[kk][3], addr);
        }
    }

    // B-fragment per-lane constants
    const u32 rowb256 = (u32)(((lane & 7) + ((lane >> 4) & 1)*8) * 256);
    const u32 hbb = (u32)((lane >> 3) & 1);

    const int r1g = q0 + wid*16 + r;
    const u32* m1 = g_mbits + ((size_t)(b*SEQ + r1g)) * 64;
    const u32* m2 = m1 + 8*64;
    const int src1 = (lane & ~3) | (t >> 1);
    const int src2 = src1 | 2;
    const bool odd = (t & 1);

    float oacc[8][4];
    #pragma unroll
    for (int i = 0; i < 8; ++i)
        #pragma unroll
        for (int j = 0; j < 4; ++j) oacc[i][j] = 0.f;
    float ls1 = 0.f, ls2 = 0.f;

    #pragma unroll 1
    for (int kt = 0; kt < 32; ++kt) {
        const int st = kt & 1;
        __syncthreads();                       // all warps done reading stage st^1
        if (kt < 31 && tid == 0) {
            const u32 mbn = (st ^ 1) ? mb1 : mb0;
            const u32 kdst = smem_base + ((st ^ 1) ? SMB_K1 : SMB_K0);
            const u32 vdst = smem_base + ((st ^ 1) ? SMB_V1 : SMB_V0);
            MBARRIER_EXPECT_TX(mbn, 32768);
            cpbulk(kdst, g_k + ((size_t)bh*32 + kt + 1)*4096, 16384, mbn);
            cpbulk(vdst, g_v + ((size_t)bh*32 + kt + 1)*4096, 16384, mbn);
        }
        if (kt > 0) {
            if (st) { MBARRIER_WAIT_PARITY(mb1, ph1); ph1 ^= 1; }
            else    { MBARRIER_WAIT_PARITY(mb0, ph0); ph0 ^= 1; }
        }

        const u32 kb = smem_base + (st ? SMB_K1 : SMB_K0) + rowb256;
        const u32 vb = smem_base + (st ? SMB_V1 : SMB_V0) + rowb256;

        #pragma unroll
        for (int half = 0; half < 2; ++half) {
            // ---- S half: 32 s-columns ----
            float sa[4][4];
            #pragma unroll
            for (int i = 0; i < 4; ++i)
                #pragma unroll
                for (int j = 0; j < 4; ++j) sa[i][j] = 0.f;
            #pragma unroll
            for (int kk = 0; kk < 8; ++kk) {
                const u32 xo = ((((u32)(kk<<1) + hbb) ^ (u32)r7) << 4);
                #pragma unroll
                for (int ntp = 0; ntp < 2; ++ntp) {
                    u32 f0, f1, f2, f3;
                    ldsm4(f0, f1, f2, f3, kb + (u32)((half*2 + ntp)*4096) + xo);
                    mma_tf32(sa[2*ntp    ], qa[kk], f0, f1);
                    mma_tf32(sa[2*ntp + 1], qa[kk], f2, f3);
                }
            }

            // ---- masked softmax (Q pre-scaled); tf32-round P, sum rounded P ----
            const u32 w1 = m1[kt*2 + half];
            const u32 w2 = m2[kt*2 + half];
            #pragma unroll
            for (int nt = 0; nt < 4; ++nt) {
                const int sh = nt*8 + 2*t;
                float p;
                p = ((w1 >> (sh  )) & 1u) ? round_tf32(ex2f(sa[nt][0])) : 0.f; sa[nt][0] = p; ls1 += p;
                p = ((w1 >> (sh+1)) & 1u) ? round_tf32(ex2f(sa[nt][1])) : 0.f; sa[nt][1] = p; ls1 += p;
                p = ((w2 >> (sh  )) & 1u) ? round_tf32(ex2f(sa[nt][2])) : 0.f; sa[nt][2] = p; ls2 += p;
                p = ((w2 >> (sh+1)) & 1u) ? round_tf32(ex2f(sa[nt][3])) : 0.f; sa[nt][3] = p; ls2 += p;
            }

            // ---- PV half ----
            #pragma unroll
            for (int jl = 0; jl < 4; ++jl) {
                const float x0 = __shfl_sync(0xffffffffu, sa[jl][0], src1);
                const float x1 = __shfl_sync(0xffffffffu, sa[jl][1], src1);
                const float x2 = __shfl_sync(0xffffffffu, sa[jl][2], src1);
                const float x3 = __shfl_sync(0xffffffffu, sa[jl][3], src1);
                const float y0 = __shfl_sync(0xffffffffu, sa[jl][0], src2);
                const float y1 = __shfl_sync(0xffffffffu, sa[jl][1], src2);
                const float y2 = __shfl_sync(0xffffffffu, sa[jl][2], src2);
                const float y3 = __shfl_sync(0xffffffffu, sa[jl][3], src2);
                u32 pa[4];
                pa[0] = __float_as_uint(odd ? x1 : x0);
                pa[1] = __float_as_uint(odd ? x3 : x2);
                pa[2] = __float_as_uint(odd ? y1 : y0);
                pa[3] = __float_as_uint(odd ? y3 : y2);
                const u32 xv = ((((u32)(half*8 + jl*2) + hbb) ^ (u32)r7) << 4);
                #pragma unroll
                for (int dnp = 0; dnp < 4; ++dnp) {
                    u32 f0, f1, f2, f3;
                    ldsm4(f0, f1, f2, f3, vb + (u32)(dnp*4096) + xv);
                    mma_tf32(oacc[2*dnp    ], pa, f0, f1);
                    mma_tf32(oacc[2*dnp + 1], pa, f2, f3);
                }
            }
        }
    }

    // ---- epilogue: quad-reduce row sums, write O/l split into tf32 hi+lo ----
    ls1 += __shfl_xor_sync(0xffffffffu, ls1, 1);
    ls1 += __shfl_xor_sync(0xffffffffu, ls1, 2);
    ls2 += __shfl_xor_sync(0xffffffffu, ls2, 1);
    ls2 += __shfl_xor_sync(0xffffffffu, ls2, 2);
    const float inv1 = 1.0f / ls1;
    const float inv2 = 1.0f / ls2;
    const size_t off1 = ((size_t)(b*SEQ + r1g    ))*DMODEL + h*64 + 2*t;
    const size_t off2 = ((size_t)(b*SEQ + r1g + 8))*DMODEL + h*64 + 2*t;
    #pragma unroll
    for (int dn = 0; dn < 8; ++dn) {
        const float v0 = oacc[dn][0]*inv1, v1 = oacc[dn][1]*inv1;
        const float v2 = oacc[dn][2]*inv2, v3 = oacc[dn][3]*inv2;
        const float h0 = round_tf32(v0), h1 = round_tf32(v1);
        const float h2 = round_tf32(v2), h3 = round_tf32(v3);
        *(float2*)(g_aoh + off1 + dn*8) = make_float2(h0, h1);
        *(float2*)(g_aol + off1 + dn*8) = make_float2(round_tf32(v0 - h0), round_tf32(v1 - h1));
        *(float2*)(g_aoh + off2 + dn*8) = make_float2(h2, h3);
        *(float2*)(g_aol + off2 + dn*8) = make_float2(round_tf32(v2 - h2), round_tf32(v3 - h3));
    }
}

// =====================================================================
// Kernel 3: output projection, 3xTF32 mma.sync (unchanged).
// =====================================================================
#define O_TILEB  18432
#define O_STAGEB (4*O_TILEB)
#define OPM_SMEM (2*O_STAGEB)

__device__ __forceinline__ void op_load(u32 smem_base, int st, int row0, int col0, int kt, int tid)
{
    const u32 sbase = smem_base + (u32)st*O_STAGEB;
    #pragma unroll
    for (int l = 0; l < 4; ++l) {
        const int i = tid + l*256;
        const int row = i >> 3, c4 = (i & 7)*4;
        const u32 off = (u32)(row*36 + c4)*4;
        const size_t ga = (size_t)(row0 + row)*DMODEL + kt*32 + c4;
        const size_t gb = (size_t)(col0 + row)*DMODEL + kt*32 + c4;
        cpa16(sbase             + off, g_aoh + ga);
        cpa16(sbase + O_TILEB   + off, g_aol + ga);
        cpa16(sbase + 2*O_TILEB + off, g_woh + gb);
        cpa16(sbase + 3*O_TILEB + off, g_wol + gb);
    }
}

__global__ __launch_bounds__(256)
void outproj_mma(const float* __restrict__ bo, float* __restrict__ out)
{
    extern __shared__ float smf[];
    const u32 smem_base = smem_u32(smf);
    const int tid = threadIdx.x;
    const int wid = tid >> 5, lane = tid & 31;
    const int r = lane >> 2, t = lane & 3;
    const int row0 = blockIdx.x * 128;
    const int col0 = blockIdx.y * 128;
    const int rw = wid*16 + r;

    op_load(smem_base, 0, row0, col0, 0, tid);
    CPA_COMMIT();

    float acc[16][4];
    #pragma unroll
    for (int i = 0; i < 16; ++i)
        #pragma unroll
        for (int j = 0; j < 4; ++j) acc[i][j] = 0.f;

    #pragma unroll 1
    for (int kt = 0; kt < 32; ++kt) {
        const int st = kt & 1;
        __syncthreads();
        if (kt < 31) { op_load(smem_base, st^1, row0, col0, kt+1, tid); CPA_COMMIT(); CPA_WAIT1(); }
        else CPA_WAIT0();
        __syncthreads();

        const float* Ah = smf + (size_t)st*O_STAGEB/4;
        const float* Al = Ah + O_TILEB/4;
        const float* Bh = Al + O_TILEB/4;
        const float* Bl = Bh + O_TILEB/4;

        #pragma unroll
        for (int kk = 0; kk < 4; ++kk) {
            const int ab = rw*36 + kk*8 + t;
            u32 ah[4], al[4];
            ah[0] = __float_as_uint(Ah[ab        ]);
            ah[1] = __float_as_uint(Ah[ab + 8*36 ]);
            ah[2] = __float_as_uint(Ah[ab + 4    ]);
            ah[3] = __float_as_uint(Ah[ab + 8*36 + 4]);
            al[0] = __float_as_uint(Al[ab        ]);
            al[1] = __float_as_uint(Al[ab + 8*36 ]);
            al[2] = __float_as_uint(Al[ab + 4    ]);
            al[3] = __float_as_uint(Al[ab + 8*36 + 4]);
            #pragma unroll
            for (int nt = 0; nt < 16; ++nt) {
                const int bb = (nt*8 + r)*36 + kk*8 + t;
                const u32 bh0 = __float_as_uint(Bh[bb    ]);
                const u32 bh1 = __float_as_uint(Bh[bb + 4]);
                const u32 bl0 = __float_as_uint(Bl[bb    ]);
                const u32 bl1 = __float_as_uint(Bl[bb + 4]);
                mma_tf32(acc[nt], ah, bh0, bh1);
                mma_tf32(acc[nt], ah, bl0, bl1);
                mma_tf32(acc[nt], al, bh0, bh1);
            }
        }
    }

    const int r1 = row0 + rw, r2 = r1 + 8;
    #pragma unroll
    for (int nt = 0; nt < 16; ++nt) {
        const int n = col0 + nt*8 + 2*t;
        const float b0 = bo[n], b1 = bo[n+1];
        *(float2*)(out + (size_t)r1*DMODEL + n) = make_float2(acc[nt][0] + b0, acc[nt][1] + b1);
        *(float2*)(out + (size_t)r2*DMODEL + n) = make_float2(acc[nt][2] + b0, acc[nt][3] + b1);
    }
}

// =====================================================================
// launch
// =====================================================================
extern "C" void kernel_launch(void* const* d_in, const int* in_sizes, int n_in,
                              void* d_out, int out_size)
{
    const float* values = (const float*)d_in[0];
    const float* keys   = (const float*)d_in[1];
    const float* query  = (const float*)d_in[2];
    const int*   mask   = (const int*)  d_in[3];
    const float* Wq     = (const float*)d_in[4];
    const float* bq     = (const float*)d_in[5];
    const float* Wk     = (const float*)d_in[6];
    const float* bk     = (const float*)d_in[7];
    const float* Wv     = (const float*)d_in[8];
    const float* bv     = (const float*)d_in[9];
    const float* Wo     = (const float*)d_in[10];
    const float* bo     = (const float*)d_in[11];
    float* out = (float*)d_out;

    cudaFuncSetAttribute(proj_mma,    cudaFuncAttributeMaxDynamicSharedMemorySize, PJ_SMEM);
    cudaFuncSetAttribute(attn_mma,    cudaFuncAttributeMaxDynamicSharedMemorySize, AT_SMEM);
    cudaFuncSetAttribute(outproj_mma, cudaFuncAttributeMaxDynamicSharedMemorySize, OPM_SMEM);

    void *pq, *pk, *pv;
    cudaGetSymbolAddress(&pq, g_q);
    cudaGetSymbolAddress(&pk, g_k);
    cudaGetSymbolAddress(&pv, g_v);

    wsplit_kernel<<<DMODEL*DMODEL/4/256, 256>>>(Wo);

    proj_mma<<<dim3(NTOK/128, 1, 3), 256, PJ_SMEM>>>(
        query, keys, values, Wq, bq, Wk, bk, Wv, bv,
        (float*)pq, (float*)pk, (float*)pv);

    maskbits_kernel<<<(BATCH*SEQ*SEQ/4)/256, 256>>>(mask);

    attn_mma<<<dim3(SEQ/128, BATCH*NH), 256, AT_SMEM>>>();

    outproj_mma<<<dim3(NTOK/128, DMODEL/128), 256, OPM_SMEM>>>(bo, out);
}

// round 14
// speedup vs baseline: 1.3372x; 1.2245x over previous
#include <cuda_runtime.h>
#include <cstdint>

#define BATCH   2
#define SEQ     2048
#define DMODEL  1024
#define NH      16
#define HD      64
#define NTOK    (BATCH*SEQ)

typedef unsigned long long ull;
typedef unsigned int u32;

#define SOFTMAX_C 0.045084220027f   // (1/32) * log2(e)

// ---------------- scratch (static device globals: allocation-free) ----------------
// Tiled + swizzled layouts (written by proj_mma, bulk-copied by attn):
//  g_q: [bh][qt=16][tile 128x64 f32]   32KB tiles
//  g_k: [bh][st=32][tile  64x64 f32]   16KB tiles
//  g_v: [bh][vt=32][tile d=64 x s=64 bf16]  8KB tiles (d-major)
__device__ float g_q  [BATCH*NH*SEQ*HD];
__device__ float g_k  [BATCH*NH*SEQ*HD];
__device__ u32   g_v  [BATCH*NH*HD*SEQ/2];
__device__ float g_aoh[NTOK*DMODEL];
__device__ float g_aol[NTOK*DMODEL];
__device__ float g_woh[DMODEL*DMODEL];
__device__ float g_wol[DMODEL*DMODEL];
__device__ u32   g_mbits[BATCH*SEQ*(SEQ/32)];

// ---------------- helpers ----------------
__device__ __forceinline__ float ex2f(float x){
    float y; asm("ex2.approx.ftz.f32 %0,%1;" : "=f"(y) : "f"(x)); return y;
}
__device__ __forceinline__ u32 cvt_tf32(float x){
    u32 y; asm("cvt.rna.tf32.f32 %0,%1;" : "=r"(y) : "f"(x)); return y;
}
__device__ __forceinline__ float round_tf32(float x){
    return __uint_as_float(cvt_tf32(x));
}
__device__ __forceinline__ u32 pkbf(float hi, float lo){
    u32 d; asm("cvt.rn.bf16x2.f32 %0,%1,%2;" : "=r"(d) : "f"(hi), "f"(lo)); return d;
}
__device__ __forceinline__ float bflo(u32 v){ return __uint_as_float(v << 16); }
__device__ __forceinline__ float bfhi(u32 v){ return __uint_as_float(v & 0xffff0000u); }

__device__ __forceinline__ void cpa16(u32 dst, const void* src){
    asm volatile("cp.async.cg.shared.global [%0], [%1], 16;" :: "r"(dst), "l"(src));
}
#define CPA_COMMIT() asm volatile("cp.async.commit_group;" ::: "memory")
#define CPA_WAIT0()  asm volatile("cp.async.wait_group 0;" ::: "memory")
#define CPA_WAIT1()  asm volatile("cp.async.wait_group 1;" ::: "memory")

__device__ __forceinline__ u32 smem_u32(const void* p){
    u32 a; asm("{ .reg .u64 t; cvta.to.shared.u64 t, %1; cvt.u32.u64 %0, t; }" : "=r"(a) : "l"(p));
    return a;
}
// mma.sync m16n8k8 tf32
__device__ __forceinline__ void mma_tf32(float* d, const u32* a, u32 b0, u32 b1){
    asm volatile("mma.sync.aligned.m16n8k8.row.col.f32.tf32.tf32.f32 "
        "{%0,%1,%2,%3},{%4,%5,%6,%7},{%8,%9},{%0,%1,%2,%3};"
        : "+f"(d[0]), "+f"(d[1]), "+f"(d[2]), "+f"(d[3])
        : "r"(a[0]), "r"(a[1]), "r"(a[2]), "r"(a[3]), "r"(b0), "r"(b1));
}
// mma.sync m16n8k16 bf16
__device__ __forceinline__ void mma_bf16(float* d, const u32* a, u32 b0, u32 b1){
    asm volatile("mma.sync.aligned.m16n8k16.row.col.f32.bf16.bf16.f32 "
        "{%0,%1,%2,%3},{%4,%5,%6,%7},{%8,%9},{%0,%1,%2,%3};"
        : "+f"(d[0]), "+f"(d[1]), "+f"(d[2]), "+f"(d[3])
        : "r"(a[0]), "r"(a[1]), "r"(a[2]), "r"(a[3]), "r"(b0), "r"(b1));
}
__device__ __forceinline__ void ldsm4(u32& r0, u32& r1, u32& r2, u32& r3, u32 addr){
    asm volatile("ldmatrix.sync.aligned.m8n8.x4.shared.b16 {%0,%1,%2,%3}, [%4];"
        : "=r"(r0), "=r"(r1), "=r"(r2), "=r"(r3) : "r"(addr));
}

// ---------------- mbarrier + bulk copy ----------------
#define MBARRIER_INIT(addr, cnt) \
    asm volatile("mbarrier.init.shared.b64 [%0], %1;" :: "r"((u32)(addr)), "r"((u32)(cnt)) : "memory")
#define MBARRIER_EXPECT_TX(addr, bytes) \
    asm volatile("mbarrier.arrive.expect_tx.shared.b64 _, [%0], %1;" :: "r"((u32)(addr)), "r"((u32)(bytes)) : "memory")
#define FENCE_PROXY_ASYNC() asm volatile("fence.proxy.async.shared::cta;" ::: "memory")
#define MBARRIER_WAIT_PARITY(mbar, parity) do { \
    u32 _m = (u32)(mbar); u32 _p = (u32)(parity); u32 _done; \
    asm volatile("{\n\t.reg .pred p;\n\t" \
        "mbarrier.try_wait.parity.acquire.cta.shared::cta.b64 p, [%1], %2;\n\t" \
        "selp.b32 %0, 1, 0, p;\n\t}" : "=r"(_done) : "r"(_m), "r"(_p) : "memory"); \
    if (!_done) { \
        asm volatile("{\n\t.reg .pred P1;\n\t" \
            "WAIT_LOOP_%=:\n\t" \
            "mbarrier.try_wait.parity.acquire.cta.shared::cta.b64 P1, [%0], %1, 0x989680;\n\t" \
            "@P1 bra.uni WAIT_DONE_%=;\n\t" \
            "bra.uni WAIT_LOOP_%=;\n\t" \
            "WAIT_DONE_%=:\n\t}" :: "r"(_m), "r"(_p) : "memory"); \
    } } while(0)

__device__ __forceinline__ void cpbulk(u32 dst, const void* src, u32 bytes, u32 mbar){
    asm volatile("cp.async.bulk.shared::cluster.global.mbarrier::complete_tx::bytes "
                 "[%0], [%1], %2, [%3];"
                 :: "r"(dst), "l"(src), "r"(bytes), "r"(mbar) : "memory");
}

// =====================================================================
// Kernel 0: split Wo into tf32 hi/lo
// =====================================================================
__global__ void wsplit_kernel(const float* __restrict__ W)
{
    const int i = blockIdx.x * 256 + threadIdx.x;
    const float4 w = ((const float4*)W)[i];
    float4 h, l;
    h.x = round_tf32(w.x); l.x = round_tf32(w.x - h.x);
    h.y = round_tf32(w.y); l.y = round_tf32(w.y - h.y);
    h.z = round_tf32(w.z); l.z = round_tf32(w.z - h.z);
    h.w = round_tf32(w.w); l.w = round_tf32(w.w - h.w);
    ((float4*)g_woh)[i] = h;
    ((float4*)g_wol)[i] = l;
}

// =====================================================================
// Kernel 1: QKV projection via tf32 mma. grid (NTOK/128, 1, 3).
// Writes tiled+swizzled layouts. Q pre-scaled by SOFTMAX_C. V bf16.
// =====================================================================
#define PJ_WST 0
#define PJ_BS  17408
#define PJ_X0  17664
#define PJ_X1  52480
#define PJ_SMEM 87296

__device__ __forceinline__ void pj_load_x(u32 xb, const float* __restrict__ x,
                                          int q0, int hofs, int tid)
{
    #pragma unroll
    for (int l2 = 0; l2 < 8; ++l2) {
        const int i = tid + l2*256;
        const int row = i >> 4, c4 = i & 15;
        cpa16(xb + (u32)(row*68 + c4*4)*4,
              x + (size_t)(q0 + row)*DMODEL + hofs + c4*4);
    }
}

__global__ __launch_bounds__(256)
void proj_mma(const float* __restrict__ xq, const float* __restrict__ xk,
              const float* __restrict__ xv,
              const float* __restrict__ Wq_, const float* __restrict__ bq_,
              const float* __restrict__ Wk_, const float* __restrict__ bk_,
              const float* __restrict__ Wv_, const float* __restrict__ bv_,
              float* __restrict__ outq, float* __restrict__ outk,
              u32* __restrict__ outv)
{
    extern __shared__ float smf[];
    const u32 smem_base = smem_u32(smf);
    const int tid = threadIdx.x;
    const int wid = tid >> 5, lane = tid & 31;
    const int r = lane >> 2, t = lane & 3;
    const int z = blockIdx.z;
    const float* x  = (z == 0) ? xq  : (z == 1) ? xk  : xv;
    const float* W  = (z == 0) ? Wq_ : (z == 1) ? Wk_ : Wv_;
    const float* bi = (z == 0) ? bq_ : (z == 1) ? bk_ : bv_;
    const float qscale = (z == 0) ? SOFTMAX_C : 1.0f;
    const int q0 = blockIdx.x * 128;
    const int bb = q0 >> 11;
    const int s0 = q0 & (SEQ - 1);
    const int rw = wid*16 + r;

    for (int idx = tid; idx < 4096; idx += 256)
        smf[PJ_WST/4 + (idx >> 6)*68 + (idx & 63)] = W[idx];
    if (tid < 64) smf[PJ_BS/4 + tid] = bi[tid];

    pj_load_x(smem_base + PJ_X0, x, q0, 0, tid);
    CPA_COMMIT();
    __syncthreads();

    for (int h = 0; h < 16; ++h) {
        const int st = h & 1;
        CPA_WAIT0();
        __syncthreads();
        if (h < 15) {
            pj_load_x(smem_base + (st ? PJ_X0 : PJ_X1), x, q0, (h+1)*64, tid);
            CPA_COMMIT();
        }

        const float* Xs = smf + (st ? PJ_X1 : PJ_X0)/4;
        u32 af[8][4];
        #pragma unroll
        for (int kk = 0; kk < 8; ++kk) {
            af[kk][0] = __float_as_uint(Xs[(rw    )*68 + kk*8 + t    ]);
            af[kk][1] = __float_as_uint(Xs[(rw + 8)*68 + kk*8 + t    ]);
            af[kk][2] = __float_as_uint(Xs[(rw    )*68 + kk*8 + t + 4]);
            af[kk][3] = __float_as_uint(Xs[(rw + 8)*68 + kk*8 + t + 4]);
        }

        float acc[8][4];
        #pragma unroll
        for (int i = 0; i < 8; ++i)
            #pragma unroll
            for (int j = 0; j < 4; ++j) acc[i][j] = 0.f;

        const float* Wt = smf + PJ_WST/4;
        #pragma unroll
        for (int kk = 0; kk < 8; ++kk) {
            #pragma unroll
            for (int nt = 0; nt < 8; ++nt) {
                const u32 b0 = __float_as_uint(Wt[(nt*8 + r)*68 + kk*8 + t    ]);
                const u32 b1 = __float_as_uint(Wt[(nt*8 + r)*68 + kk*8 + t + 4]);
                mma_tf32(acc[nt], af[kk], b0, b1);
            }
        }

        const float* bsp = smf + PJ_BS/4;
        const int xr = rw & 7;
        if (z == 0) {
            float* tb = outq + ((size_t)(bb*NH + h)*16 + (s0 >> 7))*8192;
            #pragma unroll
            for (int nt = 0; nt < 8; ++nt) {
                const int n = nt*8 + 2*t;
                const int ch = n >> 2, ii = n & 3;
                const int sw = ((ch ^ xr) * 4) + ii;
                const float b0 = bsp[n], b1 = bsp[n+1];
                *(float2*)(tb + (rw    )*64 + sw) =
                    make_float2(round_tf32((acc[nt][0]+b0)*qscale),
                                round_tf32((acc[nt][1]+b1)*qscale));
                *(float2*)(tb + (rw + 8)*64 + sw) =
                    make_float2(round_tf32((acc[nt][2]+b0)*qscale),
                                round_tf32((acc[nt][3]+b1)*qscale));
            }
        } else if (z == 1) {
            float* tb = outk + ((size_t)(bb*NH + h)*32 + (s0 >> 6) + (rw >> 6))*4096;
            const int r64 = rw & 63;
            #pragma unroll
            for (int nt = 0; nt < 8; ++nt) {
                const int n = nt*8 + 2*t;
                const int ch = n >> 2, ii = n & 3;
                const int sw = ((ch ^ xr) * 4) + ii;
                const float b0 = bsp[n], b1 = bsp[n+1];
                *(float2*)(tb + (r64    )*64 + sw) =
                    make_float2(round_tf32(acc[nt][0]+b0), round_tf32(acc[nt][1]+b1));
                *(float2*)(tb + (r64 + 8)*64 + sw) =
                    make_float2(round_tf32(acc[nt][2]+b0), round_tf32(acc[nt][3]+b1));
            }
        } else {
            // V: transpose-stage then write bf16 d-major swizzled tiles
            __syncthreads();
            float* Ts = smf + (st ? PJ_X1 : PJ_X0)/4;   // [d][tok] stride 132
            #pragma unroll
            for (int nt = 0; nt < 8; ++nt) {
                const int n = nt*8 + 2*t;
                const float b0 = bsp[n], b1 = bsp[n+1];
                Ts[(n  )*132 + rw    ] = acc[nt][0]+b0;
                Ts[(n+1)*132 + rw    ] = acc[nt][1]+b1;
                Ts[(n  )*132 + rw + 8] = acc[nt][2]+b0;
                Ts[(n+1)*132 + rw + 8] = acc[nt][3]+b1;
            }
            __syncthreads();
            #pragma unroll
            for (int l2 = 0; l2 < 4; ++l2) {
                const int idx = tid + l2*256;            // 0..1023 bf16 16B-chunks
                const int row = idx >> 4;                // d 0..63
                const int c = idx & 15;                  // 8-token chunk over 128 tokens
                const float* src = Ts + row*132 + c*8;
                const float4 f0 = *(const float4*)(src);
                const float4 f1 = *(const float4*)(src + 4);
                uint4 pk;
                pk.x = pkbf(f0.y, f0.x);
                pk.y = pkbf(f0.w, f0.z);
                pk.z = pkbf(f1.y, f1.x);
                pk.w = pkbf(f1.w, f1.z);
                const int vt = (s0 >> 6) + (c >> 3);
                const int ch = c & 7;
                u32* vb2 = outv + ((size_t)(bb*NH + h)*32 + vt)*2048;
                *(uint4*)(vb2 + row*32 + ((ch ^ (row & 7))*4)) = pk;
            }
        }
    }
}

// =====================================================================
// Kernel 1b: mask -> bitfield
// =====================================================================
__global__ void maskbits_kernel(const int* __restrict__ mask)
{
    const int gw = (blockIdx.x * 256 + threadIdx.x) >> 5;
    const int lane = threadIdx.x & 31;
    const int4 m = ((const int4*)mask)[(size_t)gw*32 + lane];
    u32 nib = (m.x ? 1u : 0u) | (m.y ? 2u : 0u) | (m.z ? 4u : 0u) | (m.w ? 8u : 0u);
    u32 val = nib << ((lane & 7) * 4);
    val |= __shfl_xor_sync(0xffffffffu, val, 1);
    val |= __shfl_xor_sync(0xffffffffu, val, 2);
    val |= __shfl_xor_sync(0xffffffffu, val, 4);
    if ((lane & 7) == 0) g_mbits[(size_t)gw*4 + (lane >> 3)] = val;
}

// =====================================================================
// Kernel 2: flash attention, 2 CTAs/SM. QK tf32, PV bf16 (C->A direct map,
// no shuffles). cp.async.bulk tile loads + mbarrier double-buffer.
// =====================================================================
#define SMB_Q  0
#define SMB_K0 32768
#define SMB_K1 49152
#define SMB_V0 65536
#define SMB_V1 73728
#define SMB_MB 81920
#define AT_SMEM 82048

__global__ __launch_bounds__(256, 2)
void attn_mma()
{
    extern __shared__ float smf[];
    const u32 smem_base = smem_u32(smf);
    const int tid = threadIdx.x;
    const int wid = tid >> 5, lane = tid & 31;
    const int r = lane >> 2, t = lane & 3;
    const int bh = blockIdx.y, b = bh >> 4, h = bh & 15;
    const int q0 = blockIdx.x * 128;
    const u32 mb0 = smem_base + SMB_MB;
    const u32 mb1 = smem_base + SMB_MB + 8;

    if (tid == 0) { MBARRIER_INIT(mb0, 1); MBARRIER_INIT(mb1, 1); FENCE_PROXY_ASYNC(); }
    __syncthreads();
    if (tid == 0) {
        MBARRIER_EXPECT_TX(mb0, 57344);
        cpbulk(smem_base + SMB_Q,  g_q + ((size_t)bh*16 + (q0 >> 7))*8192, 32768, mb0);
        cpbulk(smem_base + SMB_K0, g_k + ((size_t)bh*32)*4096, 16384, mb0);
        cpbulk(smem_base + SMB_V0, g_v + ((size_t)bh*32)*2048,  8192, mb0);
    }
    int ph0 = 0, ph1 = 0;
    MBARRIER_WAIT_PARITY(mb0, ph0); ph0 = 1;

    const int r7 = lane & 7;
    const u32 hbb = (u32)((lane >> 3) & 1);

    // ---- Q fragments, register-resident, via swizzled ldsm ----
    u32 qa[8][4];
    {
        const u32 rowa = (u32)(wid*16 + r7 + ((lane >> 3) & 1)*8);
        const u32 hba = (u32)((lane >> 4) & 1);
        #pragma unroll
        for (int kk = 0; kk < 8; ++kk) {
            const u32 addr = smem_base + SMB_Q + rowa*256 + ((((u32)(kk<<1) + hba) ^ (u32)r7) << 4);
            ldsm4(qa[kk][0], qa[kk][1], qa[kk][2], qa[kk][3], addr);
        }
    }

    // swizzle-XOR offset table (shared by K and V addressing)
    u32 xol[8];
    #pragma unroll
    for (int j = 0; j < 8; ++j)
        xol[j] = ((((u32)(j << 1)) + hbb) ^ (u32)r7) << 4;

    // per-lane row bases
    const u32 rowb256 = (u32)(((lane & 7) + ((lane >> 4) & 1)*8) * 256);  // K (f32, 256B rows)
    const u32 vrow128 = (u32)(((lane & 7) + ((lane >> 4) & 1)*8) * 128);  // V (bf16, 128B rows)

    const int r1g = q0 + wid*16 + r;
    const u32* m1 = g_mbits + ((size_t)(b*SEQ + r1g)) * 64;
    const u32* m2 = m1 + 8*64;

    float oacc[8][4];
    #pragma unroll
    for (int i = 0; i < 8; ++i)
        #pragma unroll
        for (int j = 0; j < 4; ++j) oacc[i][j] = 0.f;
    float ls1 = 0.f, ls2 = 0.f;

    #pragma unroll 1
    for (int kt = 0; kt < 32; ++kt) {
        const int st = kt & 1;
        __syncthreads();
        if (kt < 31 && tid == 0) {
            const u32 mbn = (st ^ 1) ? mb1 : mb0;
            const u32 kdst = smem_base + ((st ^ 1) ? SMB_K1 : SMB_K0);
            const u32 vdst = smem_base + ((st ^ 1) ? SMB_V1 : SMB_V0);
            MBARRIER_EXPECT_TX(mbn, 24576);
            cpbulk(kdst, g_k + ((size_t)bh*32 + kt + 1)*4096, 16384, mbn);
            cpbulk(vdst, g_v + ((size_t)bh*32 + kt + 1)*2048,  8192, mbn);
        }
        if (kt > 0) {
            if (st) { MBARRIER_WAIT_PARITY(mb1, ph1); ph1 ^= 1; }
            else    { MBARRIER_WAIT_PARITY(mb0, ph0); ph0 ^= 1; }
        }

        const u32 kb = smem_base + (st ? SMB_K1 : SMB_K0) + rowb256;
        const u32 vb = smem_base + (st ? SMB_V1 : SMB_V0) + vrow128;

        #pragma unroll
        for (int half = 0; half < 2; ++half) {
            // ---- S half: 32 s-columns, tf32 ----
            float sa[4][4];
            #pragma unroll
            for (int i = 0; i < 4; ++i)
                #pragma unroll
                for (int j = 0; j < 4; ++j) sa[i][j] = 0.f;
            #pragma unroll
            for (int kk = 0; kk < 8; ++kk) {
                #pragma unroll
                for (int ntp = 0; ntp < 2; ++ntp) {
                    u32 f0, f1, f2, f3;
                    ldsm4(f0, f1, f2, f3, kb + (u32)((half*2 + ntp)*4096) + xol[kk]);
                    mma_tf32(sa[2*ntp    ], qa[kk], f0, f1);
                    mma_tf32(sa[2*ntp + 1], qa[kk], f2, f3);
                }
            }

            // ---- masked softmax -> packed bf16 P (A-frags direct) ----
            const u32 w1 = m1[kt*2 + half];
            const u32 w2 = m2[kt*2 + half];
            #pragma unroll
            for (int nt = 0; nt < 4; ++nt) {
                const int sh = nt*8 + 2*t;
                sa[nt][0] = ((w1 >> (sh  )) & 1u) ? ex2f(sa[nt][0]) : 0.f;
                sa[nt][1] = ((w1 >> (sh+1)) & 1u) ? ex2f(sa[nt][1]) : 0.f;
                sa[nt][2] = ((w2 >> (sh  )) & 1u) ? ex2f(sa[nt][2]) : 0.f;
                sa[nt][3] = ((w2 >> (sh+1)) & 1u) ? ex2f(sa[nt][3]) : 0.f;
            }
            u32 pa[2][4];
            #pragma unroll
            for (int jj = 0; jj < 2; ++jj) {
                pa[jj][0] = pkbf(sa[2*jj    ][1], sa[2*jj    ][0]);  // (r,  k 2t,2t+1)
                pa[jj][1] = pkbf(sa[2*jj    ][3], sa[2*jj    ][2]);  // (r+8,k 2t,2t+1)
                pa[jj][2] = pkbf(sa[2*jj + 1][1], sa[2*jj + 1][0]);  // (r,  k 8+2t)
                pa[jj][3] = pkbf(sa[2*jj + 1][3], sa[2*jj + 1][2]);  // (r+8,k 8+2t)
                // ls sums use the SAME bf16-rounded values (cancellation)
                ls1 += bflo(pa[jj][0]) + bfhi(pa[jj][0]) + bflo(pa[jj][2]) + bfhi(pa[jj][2]);
                ls2 += bflo(pa[jj][1]) + bfhi(pa[jj][1]) + bflo(pa[jj][3]) + bfhi(pa[jj][3]);
            }

            // ---- PV half: bf16 k16 mmas, no shuffles ----
            #pragma unroll
            for (int jj = 0; jj < 2; ++jj) {
                const u32 xv = xol[half*2 + jj];
                #pragma unroll
                for (int dnp = 0; dnp < 4; ++dnp) {
                    u32 f0, f1, f2, f3;
                    ldsm4(f0, f1, f2, f3, vb + (u32)(dnp*2048) + xv);
                    mma_bf16(oacc[2*dnp    ], pa[jj], f0, f1);
                    mma_bf16(oacc[2*dnp + 1], pa[jj], f2, f3);
                }
            }
        }
    }

    // ---- epilogue: quad-reduce row sums, write O/l split into tf32 hi+lo ----
    ls1 += __shfl_xor_sync(0xffffffffu, ls1, 1);
    ls1 += __shfl_xor_sync(0xffffffffu, ls1, 2);
    ls2 += __shfl_xor_sync(0xffffffffu, ls2, 1);
    ls2 += __shfl_xor_sync(0xffffffffu, ls2, 2);
    const float inv1 = 1.0f / ls1;
    const float inv2 = 1.0f / ls2;
    const size_t off1 = ((size_t)(b*SEQ + r1g    ))*DMODEL + h*64 + 2*t;
    const size_t off2 = ((size_t)(b*SEQ + r1g + 8))*DMODEL + h*64 + 2*t;
    #pragma unroll
    for (int dn = 0; dn < 8; ++dn) {
        const float v0 = oacc[dn][0]*inv1, v1 = oacc[dn][1]*inv1;
        const float v2 = oacc[dn][2]*inv2, v3 = oacc[dn][3]*inv2;
        const float h0 = round_tf32(v0), h1 = round_tf32(v1);
        const float h2 = round_tf32(v2), h3 = round_tf32(v3);
        *(float2*)(g_aoh + off1 + dn*8) = make_float2(h0, h1);
        *(float2*)(g_aol + off1 + dn*8) = make_float2(round_tf32(v0 - h0), round_tf32(v1 - h1));
        *(float2*)(g_aoh + off2 + dn*8) = make_float2(h2, h3);
        *(float2*)(g_aol + off2 + dn*8) = make_float2(round_tf32(v2 - h2), round_tf32(v3 - h3));
    }
}

// =====================================================================
// Kernel 3: output projection, 3xTF32 mma.sync (unchanged).
// =====================================================================
#define O_TILEB  18432
#define O_STAGEB (4*O_TILEB)
#define OPM_SMEM (2*O_STAGEB)

__device__ __forceinline__ void op_load(u32 smem_base, int st, int row0, int col0, int kt, int tid)
{
    const u32 sbase = smem_base + (u32)st*O_STAGEB;
    #pragma unroll
    for (int l = 0; l < 4; ++l) {
        const int i = tid + l*256;
        const int row = i >> 3, c4 = (i & 7)*4;
        const u32 off = (u32)(row*36 + c4)*4;
        const size_t ga = (size_t)(row0 + row)*DMODEL + kt*32 + c4;
        const size_t gb = (size_t)(col0 + row)*DMODEL + kt*32 + c4;
        cpa16(sbase             + off, g_aoh + ga);
        cpa16(sbase + O_TILEB   + off, g_aol + ga);
        cpa16(sbase + 2*O_TILEB + off, g_woh + gb);
        cpa16(sbase + 3*O_TILEB + off, g_wol + gb);
    }
}

__global__ __launch_bounds__(256)
void outproj_mma(const float* __restrict__ bo, float* __restrict__ out)
{
    extern __shared__ float smf[];
    const u32 smem_base = smem_u32(smf);
    const int tid = threadIdx.x;
    const int wid = tid >> 5, lane = tid & 31;
    const int r = lane >> 2, t = lane & 3;
    const int row0 = blockIdx.x * 128;
    const int col0 = blockIdx.y * 128;
    const int rw = wid*16 + r;

    op_load(smem_base, 0, row0, col0, 0, tid);
    CPA_COMMIT();

    float acc[16][4];
    #pragma unroll
    for (int i = 0; i < 16; ++i)
        #pragma unroll
        for (int j = 0; j < 4; ++j) acc[i][j] = 0.f;

    #pragma unroll 1
    for (int kt = 0; kt < 32; ++kt) {
        const int st = kt & 1;
        __syncthreads();
        if (kt < 31) { op_load(smem_base, st^1, row0, col0, kt+1, tid); CPA_COMMIT(); CPA_WAIT1(); }
        else CPA_WAIT0();
        __syncthreads();

        const float* Ah = smf + (size_t)st*O_STAGEB/4;
        const float* Al = Ah + O_TILEB/4;
        const float* Bh = Al + O_TILEB/4;
        const float* Bl = Bh + O_TILEB/4;

        #pragma unroll
        for (int kk = 0; kk < 4; ++kk) {
            const int ab = rw*36 + kk*8 + t;
            u32 ah[4], al[4];
            ah[0] = __float_as_uint(Ah[ab        ]);
            ah[1] = __float_as_uint(Ah[ab + 8*36 ]);
            ah[2] = __float_as_uint(Ah[ab + 4    ]);
            ah[3] = __float_as_uint(Ah[ab + 8*36 + 4]);
            al[0] = __float_as_uint(Al[ab        ]);
            al[1] = __float_as_uint(Al[ab + 8*36 ]);
            al[2] = __float_as_uint(Al[ab + 4    ]);
            al[3] = __float_as_uint(Al[ab + 8*36 + 4]);
            #pragma unroll
            for (int nt = 0; nt < 16; ++nt) {
                const int bb = (nt*8 + r)*36 + kk*8 + t;
                const u32 bh0 = __float_as_uint(Bh[bb    ]);
                const u32 bh1 = __float_as_uint(Bh[bb + 4]);
                const u32 bl0 = __float_as_uint(Bl[bb    ]);
                const u32 bl1 = __float_as_uint(Bl[bb + 4]);
                mma_tf32(acc[nt], ah, bh0, bh1);
                mma_tf32(acc[nt], ah, bl0, bl1);
                mma_tf32(acc[nt], al, bh0, bh1);
            }
        }
    }

    const int r1 = row0 + rw, r2 = r1 + 8;
    #pragma unroll
    for (int nt = 0; nt < 16; ++nt) {
        const int n = col0 + nt*8 + 2*t;
        const float b0 = bo[n], b1 = bo[n+1];
        *(float2*)(out + (size_t)r1*DMODEL + n) = make_float2(acc[nt][0] + b0, acc[nt][1] + b1);
        *(float2*)(out + (size_t)r2*DMODEL + n) = make_float2(acc[nt][2] + b0, acc[nt][3] + b1);
    }
}

// =====================================================================
// launch
// =====================================================================
extern "C" void kernel_launch(void* const* d_in, const int* in_sizes, int n_in,
                              void* d_out, int out_size)
{
    const float* values = (const float*)d_in[0];
    const float* keys   = (const float*)d_in[1];
    const float* query  = (const float*)d_in[2];
    const int*   mask   = (const int*)  d_in[3];
    const float* Wq     = (const float*)d_in[4];
    const float* bq     = (const float*)d_in[5];
    const float* Wk     = (const float*)d_in[6];
    const float* bk     = (const float*)d_in[7];
    const float* Wv     = (const float*)d_in[8];
    const float* bv     = (const float*)d_in[9];
    const float* Wo     = (const float*)d_in[10];
    const float* bo     = (const float*)d_in[11];
    float* out = (float*)d_out;

    cudaFuncSetAttribute(proj_mma,    cudaFuncAttributeMaxDynamicSharedMemorySize, PJ_SMEM);
    cudaFuncSetAttribute(attn_mma,    cudaFuncAttributeMaxDynamicSharedMemorySize, AT_SMEM);
    cudaFuncSetAttribute(outproj_mma, cudaFuncAttributeMaxDynamicSharedMemorySize, OPM_SMEM);

    void *pq, *pk, *pv;
    cudaGetSymbolAddress(&pq, g_q);
    cudaGetSymbolAddress(&pk, g_k);
    cudaGetSymbolAddress(&pv, g_v);

    wsplit_kernel<<<DMODEL*DMODEL/4/256, 256>>>(Wo);

    proj_mma<<<dim3(NTOK/128, 1, 3), 256, PJ_SMEM>>>(
        query, keys, values, Wq, bq, Wk, bk, Wv, bv,
        (float*)pq, (float*)pk, (u32*)pv);

    maskbits_kernel<<<(BATCH*SEQ*SEQ/4)/256, 256>>>(mask);

    attn_mma<<<dim3(SEQ/128, BATCH*NH), 256, AT_SMEM>>>();

    outproj_mma<<<dim3(NTOK/128, DMODEL/128), 256, OPM_SMEM>>>(bo, out);
}

// round 15
// speedup vs baseline: 1.8721x; 1.4000x over previous
#include <cuda_runtime.h>
#include <cstdint>

#define BATCH   2
#define SEQ     2048
#define DMODEL  1024
#define NH      16
#define HD      64
#define NTOK    (BATCH*SEQ)

typedef unsigned long long ull;
typedef unsigned int u32;

#define SOFTMAX_C 0.045084220027f   // (1/32) * log2(e)

// ---------------- scratch (static device globals: allocation-free) ----------------
//  g_q: [bh][qt=16][tile 128x64 f32]   32KB tiles, XOR-swizzled
//  g_k: [bh][st=32][tile  64x64 f32]   16KB tiles, XOR-swizzled
//  g_v: [bh][vt=32][tile d=64 x s=64 bf16]  8KB tiles (d-major), XOR-swizzled
//  g_ah/g_al: attn out, bf16 hi/lo, tiles [rowtile=32][kt=32][128 rows x 80B]
//  g_wh/g_wl: Wo, bf16 hi/lo, tiles [coltile=8][kt=32][128 rows x 80B]
__device__ float g_q  [BATCH*NH*SEQ*HD];
__device__ float g_k  [BATCH*NH*SEQ*HD];
__device__ u32   g_v  [BATCH*NH*HD*SEQ/2];
__device__ u32   g_ah [32*32*2560];
__device__ u32   g_al [32*32*2560];
__device__ u32   g_wh [8*32*2560];
__device__ u32   g_wl [8*32*2560];
__device__ u32   g_mbits[BATCH*SEQ*(SEQ/32)];

// ---------------- helpers ----------------
__device__ __forceinline__ float ex2f(float x){
    float y; asm("ex2.approx.ftz.f32 %0,%1;" : "=f"(y) : "f"(x)); return y;
}
__device__ __forceinline__ u32 cvt_tf32(float x){
    u32 y; asm("cvt.rna.tf32.f32 %0,%1;" : "=r"(y) : "f"(x)); return y;
}
__device__ __forceinline__ float round_tf32(float x){
    return __uint_as_float(cvt_tf32(x));
}
__device__ __forceinline__ u32 pkbf(float hi, float lo){
    u32 d; asm("cvt.rn.bf16x2.f32 %0,%1,%2;" : "=r"(d) : "f"(hi), "f"(lo)); return d;
}
__device__ __forceinline__ float bflo(u32 v){ return __uint_as_float(v << 16); }
__device__ __forceinline__ float bfhi(u32 v){ return __uint_as_float(v & 0xffff0000u); }

__device__ __forceinline__ void cpa16(u32 dst, const void* src){
    asm volatile("cp.async.cg.shared.global [%0], [%1], 16;" :: "r"(dst), "l"(src));
}
#define CPA_COMMIT() asm volatile("cp.async.commit_group;" ::: "memory")
#define CPA_WAIT0()  asm volatile("cp.async.wait_group 0;" ::: "memory")

__device__ __forceinline__ u32 smem_u32(const void* p){
    u32 a; asm("{ .reg .u64 t; cvta.to.shared.u64 t, %1; cvt.u32.u64 %0, t; }" : "=r"(a) : "l"(p));
    return a;
}
// mma.sync m16n8k8 tf32
__device__ __forceinline__ void mma_tf32(float* d, const u32* a, u32 b0, u32 b1){
    asm volatile("mma.sync.aligned.m16n8k8.row.col.f32.tf32.tf32.f32 "
        "{%0,%1,%2,%3},{%4,%5,%6,%7},{%8,%9},{%0,%1,%2,%3};"
        : "+f"(d[0]), "+f"(d[1]), "+f"(d[2]), "+f"(d[3])
        : "r"(a[0]), "r"(a[1]), "r"(a[2]), "r"(a[3]), "r"(b0), "r"(b1));
}
// mma.sync m16n8k16 bf16
__device__ __forceinline__ void mma_bf16(float* d, const u32* a, u32 b0, u32 b1){
    asm volatile("mma.sync.aligned.m16n8k16.row.col.f32.bf16.bf16.f32 "
        "{%0,%1,%2,%3},{%4,%5,%6,%7},{%8,%9},{%0,%1,%2,%3};"
        : "+f"(d[0]), "+f"(d[1]), "+f"(d[2]), "+f"(d[3])
        : "r"(a[0]), "r"(a[1]), "r"(a[2]), "r"(a[3]), "r"(b0), "r"(b1));
}
__device__ __forceinline__ void ldsm4(u32& r0, u32& r1, u32& r2, u32& r3, u32 addr){
    asm volatile("ldmatrix.sync.aligned.m8n8.x4.shared.b16 {%0,%1,%2,%3}, [%4];"
        : "=r"(r0), "=r"(r1), "=r"(r2), "=r"(r3) : "r"(addr));
}

// ---------------- mbarrier + bulk copy ----------------
#define MBARRIER_INIT(addr, cnt) \
    asm volatile("mbarrier.init.shared.b64 [%0], %1;" :: "r"((u32)(addr)), "r"((u32)(cnt)) : "memory")
#define MBARRIER_EXPECT_TX(addr, bytes) \
    asm volatile("mbarrier.arrive.expect_tx.shared.b64 _, [%0], %1;" :: "r"((u32)(addr)), "r"((u32)(bytes)) : "memory")
#define FENCE_PROXY_ASYNC() asm volatile("fence.proxy.async.shared::cta;" ::: "memory")
#define MBARRIER_WAIT_PARITY(mbar, parity) do { \
    u32 _m = (u32)(mbar); u32 _p = (u32)(parity); u32 _done; \
    asm volatile("{\n\t.reg .pred p;\n\t" \
        "mbarrier.try_wait.parity.acquire.cta.shared::cta.b64 p, [%1], %2;\n\t" \
        "selp.b32 %0, 1, 0, p;\n\t}" : "=r"(_done) : "r"(_m), "r"(_p) : "memory"); \
    if (!_done) { \
        asm volatile("{\n\t.reg .pred P1;\n\t" \
            "WAIT_LOOP_%=:\n\t" \
            "mbarrier.try_wait.parity.acquire.cta.shared::cta.b64 P1, [%0], %1, 0x989680;\n\t" \
            "@P1 bra.uni WAIT_DONE_%=;\n\t" \
            "bra.uni WAIT_LOOP_%=;\n\t" \
            "WAIT_DONE_%=:\n\t}" :: "r"(_m), "r"(_p) : "memory"); \
    } } while(0)

__device__ __forceinline__ void cpbulk(u32 dst, const void* src, u32 bytes, u32 mbar){
    asm volatile("cp.async.bulk.shared::cluster.global.mbarrier::complete_tx::bytes "
                 "[%0], [%1], %2, [%3];"
                 :: "r"(dst), "l"(src), "r"(bytes), "r"(mbar) : "memory");
}

// =====================================================================
// Kernel 0: split Wo into bf16 hi/lo tiles [coltile][kt][128 x 80B]
// =====================================================================
__global__ void wsplit_kernel(const float* __restrict__ W)
{
    const int i = blockIdx.x * 256 + threadIdx.x;     // float4 index
    const float4 w = ((const float4*)W)[i];
    const int n = i >> 8;            // Wo row (output col) 0..1023
    const int k = (i & 255) * 4;     // 0..1020
    const u32 h0 = pkbf(w.y, w.x);
    const u32 h1 = pkbf(w.w, w.z);
    const u32 l0 = pkbf(w.y - bfhi(h0), w.x - bflo(h0));
    const u32 l1 = pkbf(w.w - bfhi(h1), w.z - bflo(h1));
    const u32 base = ((u32)((n >> 7)*32 + (k >> 5)))*2560 + (u32)((n & 127)*20) + ((u32)(k & 31) >> 1);
    g_wh[base] = h0; g_wh[base + 1] = h1;
    g_wl[base] = l0; g_wl[base + 1] = l1;
}

// =====================================================================
// Kernel 1: QKV projection via tf32 mma. grid (NTOK/128, 1, 3).
// Writes tiled+swizzled layouts. Q pre-scaled by SOFTMAX_C. V bf16.
// =====================================================================
#define PJ_WST 0
#define PJ_BS  17408
#define PJ_X0  17664
#define PJ_X1  52480
#define PJ_SMEM 87296

__device__ __forceinline__ void pj_load_x(u32 xb, const float* __restrict__ x,
                                          int q0, int hofs, int tid)
{
    #pragma unroll
    for (int l2 = 0; l2 < 8; ++l2) {
        const int i = tid + l2*256;
        const int row = i >> 4, c4 = i & 15;
        cpa16(xb + (u32)(row*68 + c4*4)*4,
              x + (size_t)(q0 + row)*DMODEL + hofs + c4*4);
    }
}

__global__ __launch_bounds__(256)
void proj_mma(const float* __restrict__ xq, const float* __restrict__ xk,
              const float* __restrict__ xv,
              const float* __restrict__ Wq_, const float* __restrict__ bq_,
              const float* __restrict__ Wk_, const float* __restrict__ bk_,
              const float* __restrict__ Wv_, const float* __restrict__ bv_,
              float* __restrict__ outq, float* __restrict__ outk,
              u32* __restrict__ outv)
{
    extern __shared__ float smf[];
    const u32 smem_base = smem_u32(smf);
    const int tid = threadIdx.x;
    const int wid = tid >> 5, lane = tid & 31;
    const int r = lane >> 2, t = lane & 3;
    const int z = blockIdx.z;
    const float* x  = (z == 0) ? xq  : (z == 1) ? xk  : xv;
    const float* W  = (z == 0) ? Wq_ : (z == 1) ? Wk_ : Wv_;
    const float* bi = (z == 0) ? bq_ : (z == 1) ? bk_ : bv_;
    const float qscale = (z == 0) ? SOFTMAX_C : 1.0f;
    const int q0 = blockIdx.x * 128;
    const int bb = q0 >> 11;
    const int s0 = q0 & (SEQ - 1);
    const int rw = wid*16 + r;

    for (int idx = tid; idx < 4096; idx += 256)
        smf[PJ_WST/4 + (idx >> 6)*68 + (idx & 63)] = W[idx];
    if (tid < 64) smf[PJ_BS/4 + tid] = bi[tid];

    pj_load_x(smem_base + PJ_X0, x, q0, 0, tid);
    CPA_COMMIT();
    __syncthreads();

    for (int h = 0; h < 16; ++h) {
        const int st = h & 1;
        CPA_WAIT0();
        __syncthreads();
        if (h < 15) {
            pj_load_x(smem_base + (st ? PJ_X0 : PJ_X1), x, q0, (h+1)*64, tid);
            CPA_COMMIT();
        }

        const float* Xs = smf + (st ? PJ_X1 : PJ_X0)/4;
        u32 af[8][4];
        #pragma unroll
        for (int kk = 0; kk < 8; ++kk) {
            af[kk][0] = __float_as_uint(Xs[(rw    )*68 + kk*8 + t    ]);
            af[kk][1] = __float_as_uint(Xs[(rw + 8)*68 + kk*8 + t    ]);
            af[kk][2] = __float_as_uint(Xs[(rw    )*68 + kk*8 + t + 4]);
            af[kk][3] = __float_as_uint(Xs[(rw + 8)*68 + kk*8 + t + 4]);
        }

        float acc[8][4];
        #pragma unroll
        for (int i = 0; i < 8; ++i)
            #pragma unroll
            for (int j = 0; j < 4; ++j) acc[i][j] = 0.f;

        const float* Wt = smf + PJ_WST/4;
        #pragma unroll
        for (int kk = 0; kk < 8; ++kk) {
            #pragma unroll
            for (int nt = 0; nt < 8; ++nt) {
                const u32 b0 = __float_as_uint(Wt[(nt*8 + r)*68 + kk*8 + t    ]);
                const u32 b1 = __float_as_uint(Wt[(nt*8 + r)*68 + kk*8 + t + 4]);
                mma_tf32(acc[nt], af[kk], b0, b1);
            }
        }

        const float* bsp = smf + PJ_BS/4;
        const int xr = rw & 7;
        if (z == 0) {
            float* tb = outq + ((size_t)(bb*NH + h)*16 + (s0 >> 7))*8192;
            #pragma unroll
            for (int nt = 0; nt < 8; ++nt) {
                const int n = nt*8 + 2*t;
                const int ch = n >> 2, ii = n & 3;
                const int sw = ((ch ^ xr) * 4) + ii;
                const float b0 = bsp[n], b1 = bsp[n+1];
                *(float2*)(tb + (rw    )*64 + sw) =
                    make_float2(round_tf32((acc[nt][0]+b0)*qscale),
                                round_tf32((acc[nt][1]+b1)*qscale));
                *(float2*)(tb + (rw + 8)*64 + sw) =
                    make_float2(round_tf32((acc[nt][2]+b0)*qscale),
                                round_tf32((acc[nt][3]+b1)*qscale));
            }
        } else if (z == 1) {
            float* tb = outk + ((size_t)(bb*NH + h)*32 + (s0 >> 6) + (rw >> 6))*4096;
            const int r64 = rw & 63;
            #pragma unroll
            for (int nt = 0; nt < 8; ++nt) {
                const int n = nt*8 + 2*t;
                const int ch = n >> 2, ii = n & 3;
                const int sw = ((ch ^ xr) * 4) + ii;
                const float b0 = bsp[n], b1 = bsp[n+1];
                *(float2*)(tb + (r64    )*64 + sw) =
                    make_float2(round_tf32(acc[nt][0]+b0), round_tf32(acc[nt][1]+b1));
                *(float2*)(tb + (r64 + 8)*64 + sw) =
                    make_float2(round_tf32(acc[nt][2]+b0), round_tf32(acc[nt][3]+b1));
            }
        } else {
            // V: transpose-stage then write bf16 d-major swizzled tiles
            __syncthreads();
            float* Ts = smf + (st ? PJ_X1 : PJ_X0)/4;   // [d][tok] stride 132
            #pragma unroll
            for (int nt = 0; nt < 8; ++nt) {
                const int n = nt*8 + 2*t;
                const float b0 = bsp[n], b1 = bsp[n+1];
                Ts[(n  )*132 + rw    ] = acc[nt][0]+b0;
                Ts[(n+1)*132 + rw    ] = acc[nt][1]+b1;
                Ts[(n  )*132 + rw + 8] = acc[nt][2]+b0;
                Ts[(n+1)*132 + rw + 8] = acc[nt][3]+b1;
            }
            __syncthreads();
            #pragma unroll
            for (int l2 = 0; l2 < 4; ++l2) {
                const int idx = tid + l2*256;
                const int row = idx >> 4;
                const int c = idx & 15;
                const float* src = Ts + row*132 + c*8;
                const float4 f0 = *(const float4*)(src);
                const float4 f1 = *(const float4*)(src + 4);
                uint4 pk;
                pk.x = pkbf(f0.y, f0.x);
                pk.y = pkbf(f0.w, f0.z);
                pk.z = pkbf(f1.y, f1.x);
                pk.w = pkbf(f1.w, f1.z);
                const int vt = (s0 >> 6) + (c >> 3);
                const int ch = c & 7;
                u32* vb2 = outv + ((size_t)(bb*NH + h)*32 + vt)*2048;
                *(uint4*)(vb2 + row*32 + ((ch ^ (row & 7))*4)) = pk;
            }
        }
    }
}

// =====================================================================
// Kernel 1b: mask -> bitfield
// =====================================================================
__global__ void maskbits_kernel(const int* __restrict__ mask)
{
    const int gw = (blockIdx.x * 256 + threadIdx.x) >> 5;
    const int lane = threadIdx.x & 31;
    const int4 m = ((const int4*)mask)[(size_t)gw*32 + lane];
    u32 nib = (m.x ? 1u : 0u) | (m.y ? 2u : 0u) | (m.z ? 4u : 0u) | (m.w ? 8u : 0u);
    u32 val = nib << ((lane & 7) * 4);
    val |= __shfl_xor_sync(0xffffffffu, val, 1);
    val |= __shfl_xor_sync(0xffffffffu, val, 2);
    val |= __shfl_xor_sync(0xffffffffu, val, 4);
    if ((lane & 7) == 0) g_mbits[(size_t)gw*4 + (lane >> 3)] = val;
}

// =====================================================================
// Kernel 2: flash attention, 2 CTAs/SM. QK tf32, PV bf16.
// Epilogue writes bf16 hi/lo into 80B-row tiles for outproj.
// =====================================================================
#define SMB_Q  0
#define SMB_K0 32768
#define SMB_K1 49152
#define SMB_V0 65536
#define SMB_V1 73728
#define SMB_MB 81920
#define AT_SMEM 82048

__global__ __launch_bounds__(256, 2)
void attn_mma()
{
    extern __shared__ float smf[];
    const u32 smem_base = smem_u32(smf);
    const int tid = threadIdx.x;
    const int wid = tid >> 5, lane = tid & 31;
    const int r = lane >> 2, t = lane & 3;
    const int bh = blockIdx.y, b = bh >> 4, h = bh & 15;
    const int q0 = blockIdx.x * 128;
    const u32 mb0 = smem_base + SMB_MB;
    const u32 mb1 = smem_base + SMB_MB + 8;

    if (tid == 0) { MBARRIER_INIT(mb0, 1); MBARRIER_INIT(mb1, 1); FENCE_PROXY_ASYNC(); }
    __syncthreads();
    if (tid == 0) {
        MBARRIER_EXPECT_TX(mb0, 57344);
        cpbulk(smem_base + SMB_Q,  g_q + ((size_t)bh*16 + (q0 >> 7))*8192, 32768, mb0);
        cpbulk(smem_base + SMB_K0, g_k + ((size_t)bh*32)*4096, 16384, mb0);
        cpbulk(smem_base + SMB_V0, g_v + ((size_t)bh*32)*2048,  8192, mb0);
    }
    int ph0 = 0, ph1 = 0;
    MBARRIER_WAIT_PARITY(mb0, ph0); ph0 = 1;

    const int r7 = lane & 7;
    const u32 hbb = (u32)((lane >> 3) & 1);

    // ---- Q fragments, register-resident, via swizzled ldsm ----
    u32 qa[8][4];
    {
        const u32 rowa = (u32)(wid*16 + r7 + ((lane >> 3) & 1)*8);
        const u32 hba = (u32)((lane >> 4) & 1);
        #pragma unroll
        for (int kk = 0; kk < 8; ++kk) {
            const u32 addr = smem_base + SMB_Q + rowa*256 + ((((u32)(kk<<1) + hba) ^ (u32)r7) << 4);
            ldsm4(qa[kk][0], qa[kk][1], qa[kk][2], qa[kk][3], addr);
        }
    }

    u32 xol[8];
    #pragma unroll
    for (int j = 0; j < 8; ++j)
        xol[j] = ((((u32)(j << 1)) + hbb) ^ (u32)r7) << 4;

    const u32 rowb256 = (u32)(((lane & 7) + ((lane >> 4) & 1)*8) * 256);
    const u32 vrow128 = (u32)(((lane & 7) + ((lane >> 4) & 1)*8) * 128);

    const int r1g = q0 + wid*16 + r;
    const u32* m1 = g_mbits + ((size_t)(b*SEQ + r1g)) * 64;
    const u32* m2 = m1 + 8*64;

    float oacc[8][4];
    #pragma unroll
    for (int i = 0; i < 8; ++i)
        #pragma unroll
        for (int j = 0; j < 4; ++j) oacc[i][j] = 0.f;
    float ls1 = 0.f, ls2 = 0.f;

    #pragma unroll 1
    for (int kt = 0; kt < 32; ++kt) {
        const int st = kt & 1;
        __syncthreads();
        if (kt < 31 && tid == 0) {
            const u32 mbn = (st ^ 1) ? mb1 : mb0;
            const u32 kdst = smem_base + ((st ^ 1) ? SMB_K1 : SMB_K0);
            const u32 vdst = smem_base + ((st ^ 1) ? SMB_V1 : SMB_V0);
            MBARRIER_EXPECT_TX(mbn, 24576);
            cpbulk(kdst, g_k + ((size_t)bh*32 + kt + 1)*4096, 16384, mbn);
            cpbulk(vdst, g_v + ((size_t)bh*32 + kt + 1)*2048,  8192, mbn);
        }
        if (kt > 0) {
            if (st) { MBARRIER_WAIT_PARITY(mb1, ph1); ph1 ^= 1; }
            else    { MBARRIER_WAIT_PARITY(mb0, ph0); ph0 ^= 1; }
        }

        const u32 kb = smem_base + (st ? SMB_K1 : SMB_K0) + rowb256;
        const u32 vb = smem_base + (st ? SMB_V1 : SMB_V0) + vrow128;

        #pragma unroll
        for (int half = 0; half < 2; ++half) {
            float sa[4][4];
            #pragma unroll
            for (int i = 0; i < 4; ++i)
                #pragma unroll
                for (int j = 0; j < 4; ++j) sa[i][j] = 0.f;
            #pragma unroll
            for (int kk = 0; kk < 8; ++kk) {
                #pragma unroll
                for (int ntp = 0; ntp < 2; ++ntp) {
                    u32 f0, f1, f2, f3;
                    ldsm4(f0, f1, f2, f3, kb + (u32)((half*2 + ntp)*4096) + xol[kk]);
                    mma_tf32(sa[2*ntp    ], qa[kk], f0, f1);
                    mma_tf32(sa[2*ntp + 1], qa[kk], f2, f3);
                }
            }

            const u32 w1 = m1[kt*2 + half];
            const u32 w2 = m2[kt*2 + half];
            #pragma unroll
            for (int nt = 0; nt < 4; ++nt) {
                const int sh = nt*8 + 2*t;
                sa[nt][0] = ((w1 >> (sh  )) & 1u) ? ex2f(sa[nt][0]) : 0.f;
                sa[nt][1] = ((w1 >> (sh+1)) & 1u) ? ex2f(sa[nt][1]) : 0.f;
                sa[nt][2] = ((w2 >> (sh  )) & 1u) ? ex2f(sa[nt][2]) : 0.f;
                sa[nt][3] = ((w2 >> (sh+1)) & 1u) ? ex2f(sa[nt][3]) : 0.f;
            }
            u32 pa[2][4];
            #pragma unroll
            for (int jj = 0; jj < 2; ++jj) {
                pa[jj][0] = pkbf(sa[2*jj    ][1], sa[2*jj    ][0]);
                pa[jj][1] = pkbf(sa[2*jj    ][3], sa[2*jj    ][2]);
                pa[jj][2] = pkbf(sa[2*jj + 1][1], sa[2*jj + 1][0]);
                pa[jj][3] = pkbf(sa[2*jj + 1][3], sa[2*jj + 1][2]);
                ls1 += bflo(pa[jj][0]) + bfhi(pa[jj][0]) + bflo(pa[jj][2]) + bfhi(pa[jj][2]);
                ls2 += bflo(pa[jj][1]) + bfhi(pa[jj][1]) + bflo(pa[jj][3]) + bfhi(pa[jj][3]);
            }

            #pragma unroll
            for (int jj = 0; jj < 2; ++jj) {
                const u32 xv = xol[half*2 + jj];
                #pragma unroll
                for (int dnp = 0; dnp < 4; ++dnp) {
                    u32 f0, f1, f2, f3;
                    ldsm4(f0, f1, f2, f3, vb + (u32)(dnp*2048) + xv);
                    mma_bf16(oacc[2*dnp    ], pa[jj], f0, f1);
                    mma_bf16(oacc[2*dnp + 1], pa[jj], f2, f3);
                }
            }
        }
    }

    // ---- epilogue: quad-reduce sums, write bf16 hi/lo into 80B-row tiles ----
    ls1 += __shfl_xor_sync(0xffffffffu, ls1, 1);
    ls1 += __shfl_xor_sync(0xffffffffu, ls1, 2);
    ls2 += __shfl_xor_sync(0xffffffffu, ls2, 1);
    ls2 += __shfl_xor_sync(0xffffffffu, ls2, 2);
    const float inv1 = 1.0f / ls1;
    const float inv2 = 1.0f / ls2;
    const int rowtile = (b*SEQ + q0) >> 7;
    const int rowin1 = wid*16 + r;
    const int rowin2 = rowin1 + 8;
    #pragma unroll
    for (int dn = 0; dn < 8; ++dn) {
        const int n = dn*8 + 2*t;
        const int kt2 = h*2 + (n >> 5);
        const u32 base = ((u32)(rowtile*32 + kt2))*2560 + ((u32)(n & 31) >> 1);
        const float v0 = oacc[dn][0]*inv1, v1 = oacc[dn][1]*inv1;
        const float v2 = oacc[dn][2]*inv2, v3 = oacc[dn][3]*inv2;
        const u32 hp1 = pkbf(v1, v0);
        const u32 lp1 = pkbf(v1 - bfhi(hp1), v0 - bflo(hp1));
        const u32 hp2 = pkbf(v3, v2);
        const u32 lp2 = pkbf(v3 - bfhi(hp2), v2 - bflo(hp2));
        g_ah[base + (u32)rowin1*20] = hp1;
        g_al[base + (u32)rowin1*20] = lp1;
        g_ah[base + (u32)rowin2*20] = hp2;
        g_al[base + (u32)rowin2*20] = lp2;
    }
}

// =====================================================================
// Kernel 3: output projection, bf16 hi/lo 3-term, bulk copies + ldmatrix.
// grid (32 rowtiles, 8 coltiles). 2 CTAs/SM.
// =====================================================================
#define OPB_AL 10240
#define OPB_BH 20480
#define OPB_BL 30720
#define OPB_STAGE 40960
#define OPB_MB 81920
#define OPM_SMEM 82048

__global__ __launch_bounds__(256, 2)
void outproj_mma(const float* __restrict__ bo, float* __restrict__ out)
{
    extern __shared__ float smf[];
    const u32 smem_base = smem_u32(smf);
    const int tid = threadIdx.x;
    const int wid = tid >> 5, lane = tid & 31;
    const int r = lane >> 2, t = lane & 3;
    const int rowtile = blockIdx.x;
    const int coltile = blockIdx.y;
    const u32 mb0 = smem_base + OPB_MB;
    const u32 mb1 = smem_base + OPB_MB + 8;

    if (tid == 0) { MBARRIER_INIT(mb0, 1); MBARRIER_INIT(mb1, 1); FENCE_PROXY_ASYNC(); }
    __syncthreads();
    if (tid == 0) {
        MBARRIER_EXPECT_TX(mb0, 40960);
        cpbulk(smem_base          , g_ah + (size_t)(rowtile*32)*2560, 10240, mb0);
        cpbulk(smem_base + OPB_AL , g_al + (size_t)(rowtile*32)*2560, 10240, mb0);
        cpbulk(smem_base + OPB_BH , g_wh + (size_t)(coltile*32)*2560, 10240, mb0);
        cpbulk(smem_base + OPB_BL , g_wl + (size_t)(coltile*32)*2560, 10240, mb0);
    }
    int ph0 = 0, ph1 = 0;
    MBARRIER_WAIT_PARITY(mb0, ph0); ph0 = 1;

    // A-frag per-lane address (rows m): lanes 8-15 -> +8 rows, lanes>=16 -> +16B
    const u32 arow_off = (u32)((wid*16 + (lane & 7) + ((lane >> 3) & 1)*8) * 80
                               + ((lane >> 4) & 1)*16);
    // B-frag per-lane address (rows n): lanes>=16 -> +8 rows, bit3 -> +16B (k half)
    const u32 blane = (u32)(((lane & 7) + ((lane >> 4) & 1)*8) * 80
                            + ((lane >> 3) & 1)*16);

    float acc[16][4];
    #pragma unroll
    for (int i = 0; i < 16; ++i)
        #pragma unroll
        for (int j = 0; j < 4; ++j) acc[i][j] = 0.f;

    #pragma unroll 1
    for (int kt = 0; kt < 32; ++kt) {
        const int st = kt & 1;
        __syncthreads();
        if (kt < 31 && tid == 0) {
            const u32 mbn = (st ^ 1) ? mb1 : mb0;
            const u32 db = smem_base + ((st ^ 1) ? OPB_STAGE : 0);
            MBARRIER_EXPECT_TX(mbn, 40960);
            cpbulk(db          , g_ah + (size_t)(rowtile*32 + kt + 1)*2560, 10240, mbn);
            cpbulk(db + OPB_AL , g_al + (size_t)(rowtile*32 + kt + 1)*2560, 10240, mbn);
            cpbulk(db + OPB_BH , g_wh + (size_t)(coltile*32 + kt + 1)*2560, 10240, mbn);
            cpbulk(db + OPB_BL , g_wl + (size_t)(coltile*32 + kt + 1)*2560, 10240, mbn);
        }
        if (kt > 0) {
            if (st) { MBARRIER_WAIT_PARITY(mb1, ph1); ph1 ^= 1; }
            else    { MBARRIER_WAIT_PARITY(mb0, ph0); ph0 ^= 1; }
        }

        const u32 sb = smem_base + (st ? OPB_STAGE : 0);
        const u32 Ahb = sb + arow_off;
        const u32 Alb = sb + OPB_AL + arow_off;
        const u32 Bhb = sb + OPB_BH + blane;
        const u32 Blb = sb + OPB_BL + blane;

        #pragma unroll
        for (int c = 0; c < 2; ++c) {
            u32 ah[4], al[4];
            ldsm4(ah[0], ah[1], ah[2], ah[3], Ahb + c*32);
            ldsm4(al[0], al[1], al[2], al[3], Alb + c*32);
            #pragma unroll
            for (int p = 0; p < 8; ++p) {
                u32 f0, f1, f2, f3, g0, g1, g2, g3;
                ldsm4(f0, f1, f2, f3, Bhb + (u32)(p*1280) + c*32);
                ldsm4(g0, g1, g2, g3, Blb + (u32)(p*1280) + c*32);
                mma_bf16(acc[2*p    ], ah, f0, f1);
                mma_bf16(acc[2*p    ], ah, g0, g1);
                mma_bf16(acc[2*p    ], al, f0, f1);
                mma_bf16(acc[2*p + 1], ah, f2, f3);
                mma_bf16(acc[2*p + 1], ah, g2, g3);
                mma_bf16(acc[2*p + 1], al, f2, f3);
            }
        }
    }

    const int r1 = rowtile*128 + wid*16 + r;
    const int r2 = r1 + 8;
    #pragma unroll
    for (int nt = 0; nt < 16; ++nt) {
        const int n = coltile*128 + nt*8 + 2*t;
        const float b0 = bo[n], b1 = bo[n+1];
        *(float2*)(out + (size_t)r1*DMODEL + n) = make_float2(acc[nt][0] + b0, acc[nt][1] + b1);
        *(float2*)(out + (size_t)r2*DMODEL + n) = make_float2(acc[nt][2] + b0, acc[nt][3] + b1);
    }
}

// =====================================================================
// launch
// =====================================================================
extern "C" void kernel_launch(void* const* d_in, const int* in_sizes, int n_in,
                              void* d_out, int out_size)
{
    const float* values = (const float*)d_in[0];
    const float* keys   = (const float*)d_in[1];
    const float* query  = (const float*)d_in[2];
    const int*   mask   = (const int*)  d_in[3];
    const float* Wq     = (const float*)d_in[4];
    const float* bq     = (const float*)d_in[5];
    const float* Wk     = (const float*)d_in[6];
    const float* bk     = (const float*)d_in[7];
    const float* Wv     = (const float*)d_in[8];
    const float* bv     = (const float*)d_in[9];
    const float* Wo     = (const float*)d_in[10];
    const float* bo     = (const float*)d_in[11];
    float* out = (float*)d_out;

    cudaFuncSetAttribute(proj_mma,    cudaFuncAttributeMaxDynamicSharedMemorySize, PJ_SMEM);
    cudaFuncSetAttribute(attn_mma,    cudaFuncAttributeMaxDynamicSharedMemorySize, AT_SMEM);
    cudaFuncSetAttribute(outproj_mma, cudaFuncAttributeMaxDynamicSharedMemorySize, OPM_SMEM);

    void *pq, *pk, *pv;
    cudaGetSymbolAddress(&pq, g_q);
    cudaGetSymbolAddress(&pk, g_k);
    cudaGetSymbolAddress(&pv, g_v);

    wsplit_kernel<<<DMODEL*DMODEL/4/256, 256>>>(Wo);

    proj_mma<<<dim3(NTOK/128, 1, 3), 256, PJ_SMEM>>>(
        query, keys, values, Wq, bq, Wk, bk, Wv, bv,
        (float*)pq, (float*)pk, (u32*)pv);

    maskbits_kernel<<<(BATCH*SEQ*SEQ/4)/256, 256>>>(mask);

    attn_mma<<<dim3(SEQ/128, BATCH*NH), 256, AT_SMEM>>>();

    outproj_mma<<<dim3(32, 8), 256, OPM_SMEM>>>(bo, out);
}